// round 13
// baseline (speedup 1.0000x reference)
#include <cuda_runtime.h>
#include <math.h>
#include <float.h>

#define BB 2
#define SEQ 2048
#define DIM 1024
#define FF 2816
#define NTOK (BB*SEQ)
#define WIN 512
#define OUTV 32000
#define SPACE 36
#define QKVS 3072
#define FF2  5632

#define DD   (DIM*DIM)          // 1048576
#define DF   (DIM*FF)           // 2883584
#define LWS  (4*DD + 3*DF)      // per-layer weight floats
#define WTOT (2*LWS + DIM*OUTV) // all rounded weights

// ---------------- scratch (device globals; no allocation allowed) ----------------
__device__ float g_embeds[NTOK*DIM];
__device__ float g_h[NTOK*DIM];
__device__ float g_xn[NTOK*DIM];
__device__ float g_qkv[(size_t)NTOK*QKVS];
__device__ float g_attn[NTOK*DIM];
__device__ float g_f13[(size_t)NTOK*FF2];
__device__ float g_f1[(size_t)NTOK*FF];
__device__ float g_pool[NTOK*DIM];
__device__ float g_wt[WTOT];
__device__ int   g_pid[NTOK];
__device__ int   g_pstart[NTOK];
__device__ int   g_np[BB];

__device__ __forceinline__ float rtf(float x){
    unsigned r;
    asm("cvt.rna.tf32.f32 %0, %1;" : "=r"(r) : "f"(x));
    return __uint_as_float(r);
}

// ---------------- round fp32 -> tf32-snapped fp32, with column-packing ----------------
__global__ __launch_bounds__(256) void k_round(const float* __restrict__ s,
        float* __restrict__ d, int n4, int ncols4, int totcols4, int coloff4){
    int stride = gridDim.x * 256;
    int e = blockIdx.x*256 + threadIdx.x;
    float4 v[4]; int idx[4]; int cnt = 0;
    #pragma unroll
    for (int i = 0; i < 4; i++){
        int ix = e + i*stride;
        if (ix < n4){ v[cnt] = ((const float4*)s)[ix]; idx[cnt] = ix; cnt++; }
    }
    #pragma unroll
    for (int i = 0; i < 4; i++){
        if (i < cnt){
            float4 w = v[i];
            w.x = rtf(w.x); w.y = rtf(w.y); w.z = rtf(w.z); w.w = rtf(w.w);
            int k = idx[i] / ncols4;
            int c = idx[i] - k*ncols4;
            ((float4*)d)[(size_t)k*totcols4 + coloff4 + c] = w;
        }
    }
}

// ---------------- hash n-gram embeddings ----------------
__global__ __launch_bounds__(256) void k_hash_embed(const int* __restrict__ ids,
        const float* __restrict__ tok_emb, const float* __restrict__ hash_emb){
    int bs = blockIdx.x; int b = bs / SEQ; int i = bs - b*SEQ;
    const int* row = ids + b*SEQ;
    unsigned gg[4];
    #pragma unroll
    for (int j = 0; j < 4; j++) gg[j] = (i >= j) ? (unsigned)row[i-j] : 0u;
    const unsigned mult[3] = {2654435761u, 805459861u, 2246822519u};
    const float* src0 = tok_emb + (size_t)row[i]*DIM;
    const float* srch[3];
    #pragma unroll
    for (int f = 0; f < 3; f++){
        unsigned a = mult[f], h = 0u;
        #pragma unroll
        for (int j = 0; j < 4; j++) h = h*a + gg[j];
        srch[f] = hash_emb + ((size_t)f*32000u + (h % 32000u))*DIM;
    }
    int d = threadIdx.x*4;
    float4 v = *(const float4*)(src0 + d);
    #pragma unroll
    for (int f = 0; f < 3; f++){
        float4 w = *(const float4*)(srch[f] + d);
        v.x += w.x; v.y += w.y; v.z += w.z; v.w += w.w;
    }
    size_t o = (size_t)bs*DIM + d;
    *(float4*)(g_embeds + o) = v;
    *(float4*)(g_h + o) = v;
}

// ---------------- patch ids via warp scan (1 warp per batch) ----------------
__global__ void k_patch(const int* __restrict__ ids){
    int b = threadIdx.x >> 5;
    int lane = threadIdx.x & 31;
    if (b >= BB) return;
    const int* row = ids + b*SEQ;
    int base = 0;
    for (int c = 0; c < SEQ; c += 32){
        int i = c + lane;
        int s = (i == 0) || (row[i-1] == SPACE);
        unsigned m = __ballot_sync(0xffffffffu, s);
        int pid = base + __popc(m & (0xffffffffu >> (31 - lane))) - 1;
        g_pid[b*SEQ + i] = pid;
        if (s) g_pstart[b*SEQ + pid] = i;
        base += __popc(m);
    }
    if (lane == 0) g_np[b] = base;
}

// ---------------- rmsnorm: g_h -> g_xn (output tf32-snapped) ----------------
__global__ __launch_bounds__(256) void k_rmsnorm(const float* __restrict__ w){
    int rowi = blockIdx.x;
    int tid = threadIdx.x;
    size_t base = (size_t)rowi*DIM + tid*4;
    float4 v = *(const float4*)(g_h + base);
    float ss = v.x*v.x + v.y*v.y + v.z*v.z + v.w*v.w;
    #pragma unroll
    for (int o = 16; o; o >>= 1) ss += __shfl_xor_sync(0xffffffffu, ss, o);
    __shared__ float red[8];
    if ((tid & 31) == 0) red[tid >> 5] = ss;
    __syncthreads();
    float tot = red[0]+red[1]+red[2]+red[3]+red[4]+red[5]+red[6]+red[7];
    float r = rsqrtf(tot * (1.0f/DIM) + 1e-5f);
    float4 wv = *(const float4*)(w + tid*4);
    float4 o4;
    o4.x = rtf(v.x*r*wv.x); o4.y = rtf(v.y*r*wv.y);
    o4.z = rtf(v.z*r*wv.z); o4.w = rtf(v.w*r*wv.w);
    *(float4*)(g_xn + base) = o4;
}

#define CP_ASYNC16(dst, src) \
    asm volatile("cp.async.cg.shared.global [%0], [%1], 16;\n" :: "r"(dst), "l"(src))
#define CP_COMMIT() asm volatile("cp.async.commit_group;\n" ::)

#define MMA_TF32(acc, a0,a1,a2,a3, b0,b1) \
    asm volatile( \
        "mma.sync.aligned.m16n8k8.row.col.f32.tf32.tf32.f32 " \
        "{%0,%1,%2,%3}, {%4,%5,%6,%7}, {%8,%9}, {%0,%1,%2,%3};" \
        : "+f"((acc)[0]), "+f"((acc)[1]), "+f"((acc)[2]), "+f"((acc)[3]) \
        : "r"(a0), "r"(a1), "r"(a2), "r"(a3), "r"(b0), "r"(b1))

// ---------------- tf32 tensor-core GEMM: 128x128x16 tile, 4 warps of 64x64 ----------------
// Same tile / smem layout / pipeline as the proven kernel, but warp tiles are
// 64x64 -> 64 LDS : 64 MMA per warp-tile (was 96:64). 128 threads, 2 CTA/SM.
#define GSMEM (4*(128*20 + 16*136)*4)

__global__ __launch_bounds__(128, 2) void k_gemm(const float* __restrict__ A,
        const float* __restrict__ Bm, float* __restrict__ C,
        const float* __restrict__ R, int N, int K, int addres){
    extern __shared__ __align__(16) float smem[];
    float (*As)[128][20] = (float(*)[128][20])smem;
    float (*Bs)[16][136] = (float(*)[16][136])(smem + 4*128*20);

    const int m0 = blockIdx.x * 128, n0 = blockIdx.y * 128;
    const int tid = threadIdx.x;
    const int wid = tid >> 5, lane = tid & 31;
    const int wm = (wid >> 1) * 64;          // 2 m-groups
    const int wn = (wid & 1) * 64;           // 2 n-groups
    const int g = lane >> 2, tg = lane & 3;

    // A loader: 4 passes, 32 rows/pass, 4 lanes per row (64B runs, coalesced)
    const int arow = tid >> 2, acol = (tid & 3) * 4;
    // B loader: 2 passes, 8 rows/pass, 16 lanes per row (512B contiguous)
    const int brow = tid >> 4, bcol = (tid & 15) * 8;
    const float* Abase = A + (size_t)(m0 + arow)*K + acol;
    const float* Bbase = Bm + (size_t)brow*N + n0 + bcol;

    float acc[4][8][4];
    #pragma unroll
    for (int i = 0; i < 4; i++)
        #pragma unroll
        for (int j = 0; j < 8; j++)
            #pragma unroll
            for (int c = 0; c < 4; c++) acc[i][j][c] = 0.0f;

#define LOADSTAGE(st, k0) do { \
        _Pragma("unroll") \
        for (int rr = 0; rr < 4; rr++){ \
            unsigned da = (unsigned)__cvta_generic_to_shared(&As[st][arow + rr*32][acol]); \
            CP_ASYNC16(da, Abase + (size_t)(rr*32)*K + (k0)); \
        } \
        _Pragma("unroll") \
        for (int rr = 0; rr < 2; rr++){ \
            unsigned db0 = (unsigned)__cvta_generic_to_shared(&Bs[st][brow + rr*8][bcol]); \
            CP_ASYNC16(db0, Bbase + (size_t)((k0) + rr*8)*N); \
            unsigned db1 = (unsigned)__cvta_generic_to_shared(&Bs[st][brow + rr*8][bcol+4]); \
            CP_ASYNC16(db1, Bbase + (size_t)((k0) + rr*8)*N + 4); \
        } \
        CP_COMMIT(); \
    } while(0)

    const int KT = K >> 4;
    LOADSTAGE(0, 0);
    LOADSTAGE(1, 16);
    LOADSTAGE(2, 32);

    for (int kt = 0; kt < KT; kt++){
        const int s = kt & 3;
        const int rem = KT - 1 - kt;
        if (rem >= 2)      asm volatile("cp.async.wait_group 2;\n" ::);
        else if (rem == 1) asm volatile("cp.async.wait_group 1;\n" ::);
        else               asm volatile("cp.async.wait_group 0;\n" ::);
        __syncthreads();
        if (kt + 3 < KT) LOADSTAGE((kt+3) & 3, (kt+3) << 4);

        #pragma unroll
        for (int kk = 0; kk < 16; kk += 8){
            unsigned af[4][4], bf[8][2];
            #pragma unroll
            for (int i = 0; i < 4; i++){
                int r = wm + i*16;
                af[i][0] = __float_as_uint(As[s][r+g   ][kk+tg  ]);
                af[i][1] = __float_as_uint(As[s][r+g+8 ][kk+tg  ]);
                af[i][2] = __float_as_uint(As[s][r+g   ][kk+tg+4]);
                af[i][3] = __float_as_uint(As[s][r+g+8 ][kk+tg+4]);
            }
            #pragma unroll
            for (int j = 0; j < 8; j++){
                int cl = wn + j*8 + g;
                bf[j][0] = __float_as_uint(Bs[s][kk+tg  ][cl]);
                bf[j][1] = __float_as_uint(Bs[s][kk+tg+4][cl]);
            }
            #pragma unroll
            for (int i = 0; i < 4; i++)
                #pragma unroll
                for (int j = 0; j < 8; j++)
                    MMA_TF32(acc[i][j], af[i][0],af[i][1],af[i][2],af[i][3],
                             bf[j][0],bf[j][1]);
        }
    }

    #pragma unroll
    for (int i = 0; i < 4; i++){
        #pragma unroll
        for (int j = 0; j < 8; j++){
            size_t off = (size_t)(m0 + wm + i*16 + g)*N + n0 + wn + j*8 + tg*2;
            float2 r0 = make_float2(acc[i][j][0], acc[i][j][1]);
            float2 r1 = make_float2(acc[i][j][2], acc[i][j][3]);
            if (addres){
                float2 q0 = *(const float2*)(R + off);
                float2 q1 = *(const float2*)(R + off + (size_t)8*N);
                r0.x += q0.x; r0.y += q0.y; r1.x += q1.x; r1.y += q1.y;
            }
            *(float2*)(C + off) = r0;
            *(float2*)(C + off + (size_t)8*N) = r1;
        }
    }
}

// ---------------- RoPE (in place on q,k inside g_qkv) ----------------
__global__ __launch_bounds__(256) void k_rope(){
    int bs = blockIdx.x;
    int pos = bs & (SEQ - 1);
    size_t base = (size_t)bs*QKVS;
    for (int d = threadIdx.x; d < 512; d += 256){
        float freq = powf(10000.0f, -(float)d * (1.0f/512.0f));
        float ang = (float)pos * freq;
        float sn, cs;
        sincosf(ang, &sn, &cs);
        float x1 = g_qkv[base + d], x2 = g_qkv[base + 512 + d];
        g_qkv[base + d]       = x1*cs - x2*sn;
        g_qkv[base + 512 + d] = x1*sn + x2*cs;
        x1 = g_qkv[base + 1024 + d]; x2 = g_qkv[base + 1536 + d];
        g_qkv[base + 1024 + d] = x1*cs - x2*sn;
        g_qkv[base + 1536 + d] = x1*sn + x2*cs;
    }
}

// ---------------- fused windowed causal attention, 16-query tiles ----------------
#define QT 16
#define SPAN 544
__global__ __launch_bounds__(128) void k_attn(){
    __shared__ __align__(16) float Ssh[QT*SPAN];   // 34.8 KB
    __shared__ __align__(16) float stage[4752];    // 19 KB
    float* Qs = stage;            // [16][33]
    float* Ks = stage + 16*33;    // [128][33]
    float* Vs = stage;            // [32][136] in pass 2
    int tile = blockIdx.x;
    int b = tile / (SEQ/QT);
    int i0 = (tile - b*(SEQ/QT)) * QT;
    int tid = threadIdx.x;
    int tq = tid >> 5, tk = tid & 31;      // warp 0..3, lane
    int kmin = i0 - (WIN - 1); if (kmin < 0) kmin = 0;
    int span = i0 + QT - kmin;                       // <= 527
    int spanw = ((span + 63) >> 6) << 6;
    if (spanw > SPAN) spanw = SPAN;
    int lastkey = i0 + QT - 1;

    // ---- pass 1: scores = Q K^T / 32 (banded, masked) ----
    for (int kc0 = 0; kc0 < span; kc0 += 128){
        float c[4][4];
        #pragma unroll
        for (int u = 0; u < 4; u++)
            #pragma unroll
            for (int v = 0; v < 4; v++) c[u][v] = 0.f;
        for (int dc = 0; dc < DIM; dc += 32){
            int r = tid >> 3, cb = (tid & 7) << 2;   // r in [0,16), cb in {0..28}
            {
                float4 qv = *(const float4*)(g_qkv + ((size_t)(b*SEQ + i0 + r))*QKVS + dc + cb);
                float* qp = Qs + r*33 + cb;
                qp[0]=qv.x; qp[1]=qv.y; qp[2]=qv.z; qp[3]=qv.w;
            }
            #pragma unroll
            for (int h = 0; h < 8; h++){             // K: 128 rows
                int rr = r + h*16;
                int key = kmin + kc0 + rr; if (key > lastkey) key = lastkey;
                float4 kv = *(const float4*)(g_qkv + ((size_t)(b*SEQ + key))*QKVS + 1024 + dc + cb);
                float* kp = Ks + rr*33 + cb;
                kp[0]=kv.x; kp[1]=kv.y; kp[2]=kv.z; kp[3]=kv.w;
            }
            __syncthreads();
            #pragma unroll
            for (int d = 0; d < 32; d++){
                float a0 = Qs[(tq*4  )*33 + d];
                float a1 = Qs[(tq*4+1)*33 + d];
                float a2 = Qs[(tq*4+2)*33 + d];
                float a3 = Qs[(tq*4+3)*33 + d];
                #pragma unroll
                for (int v = 0; v < 4; v++){
                    float bv = Ks[(tk + 32*v)*33 + d];
                    c[0][v] += a0*bv;
                    c[1][v] += a1*bv;
                    c[2][v] += a2*bv;
                    c[3][v] += a3*bv;
                }
            }
            __syncthreads();
        }
        #pragma unroll
        for (int u = 0; u < 4; u++){
            int qa = i0 + tq*4 + u;
            #pragma unroll
            for (int v = 0; v < 4; v++){
                int jr = kc0 + tk + 32*v;
                if (jr < SPAN){
                    int ja = kmin + jr;
                    bool ok = (jr < span) && (ja <= qa) && (qa - ja < WIN);
                    Ssh[(tq*4+u)*SPAN + jr] = ok ? c[u][v]*0.03125f : -1e30f;
                }
            }
        }
    }
    __syncthreads();

    // ---- softmax (4 warps, 4 rows each) ----
    for (int q = tq; q < QT; q += 4){
        float* sr = Ssh + q*SPAN;
        float mx = -1e30f;
        for (int j = tk; j < spanw; j += 32) mx = fmaxf(mx, sr[j]);
        #pragma unroll
        for (int o = 16; o; o >>= 1) mx = fmaxf(mx, __shfl_xor_sync(0xffffffffu, mx, o));
        float sm = 0.f;
        for (int j = tk; j < spanw; j += 32){
            float p = expf(sr[j] - mx); sr[j] = p; sm += p;
        }
        #pragma unroll
        for (int o = 16; o; o >>= 1) sm += __shfl_xor_sync(0xffffffffu, sm, o);
        float inv = 1.0f/sm;
        for (int j = tk; j < spanw; j += 32) sr[j] *= inv;
    }
    __syncthreads();

    // ---- pass 2: O = P @ V (output tf32-snapped for the wo GEMM) ----
    for (int n0 = 0; n0 < DIM; n0 += 128){
        float o[4][4];
        #pragma unroll
        for (int u = 0; u < 4; u++)
            #pragma unroll
            for (int v = 0; v < 4; v++) o[u][v] = 0.f;
        for (int kc0 = 0; kc0 < span; kc0 += 32){
            int r = tid >> 3, cb = (tid & 7) << 4;   // 16 floats per thread
            #pragma unroll
            for (int h = 0; h < 2; h++){             // 32 rows
                int rr = r + h*16;
                int key = kmin + kc0 + rr; if (key > lastkey) key = lastkey;
                const float* vp = g_qkv + ((size_t)(b*SEQ + key))*QKVS + 2048 + n0 + cb;
                #pragma unroll
                for (int t4 = 0; t4 < 4; t4++){
                    *(float4*)(Vs + rr*136 + cb + t4*4) = *(const float4*)(vp + t4*4);
                }
            }
            __syncthreads();
            const float* p0r = Ssh + (tq*4)*SPAN + kc0;
            #pragma unroll
            for (int jj = 0; jj < 32; jj++){
                float p0 = p0r[jj];
                float p1 = p0r[jj + SPAN];
                float p2 = p0r[jj + 2*SPAN];
                float p3 = p0r[jj + 3*SPAN];
                #pragma unroll
                for (int v = 0; v < 4; v++){
                    float vv = Vs[jj*136 + tk + 32*v];
                    o[0][v] += p0*vv;
                    o[1][v] += p1*vv;
                    o[2][v] += p2*vv;
                    o[3][v] += p3*vv;
                }
            }
            __syncthreads();
        }
        #pragma unroll
        for (int u = 0; u < 4; u++){
            size_t ob = ((size_t)(b*SEQ + i0 + tq*4 + u))*DIM + n0;
            #pragma unroll
            for (int v = 0; v < 4; v++)
                g_attn[ob + tk + 32*v] = rtf(o[u][v]);
        }
    }
}

// ---------------- silu(f13[:, :FF]) * f13[:, FF:] -> f1 (tf32-snapped) ----------------
__global__ __launch_bounds__(704) void k_silu(){
    int row = blockIdx.x;
    int col = threadIdx.x * 4;
    size_t src = (size_t)row*FF2 + col;
    float4 a = *(float4*)(g_f13 + src);
    float4 c = *(float4*)(g_f13 + src + FF);
    a.x = rtf(a.x/(1.f + expf(-a.x))*c.x);
    a.y = rtf(a.y/(1.f + expf(-a.y))*c.y);
    a.z = rtf(a.z/(1.f + expf(-a.z))*c.z);
    a.w = rtf(a.w/(1.f + expf(-a.w))*c.w);
    *(float4*)(g_f1 + (size_t)row*FF + col) = a;
}

// ---------------- segment max pooling (runs are contiguous) ----------------
__global__ __launch_bounds__(256) void k_pool(){
    int b = blockIdx.y, p = blockIdx.x;
    int np = g_np[b];
    if (p >= np) return;
    int i0 = g_pstart[b*SEQ + p];
    int i1 = (p + 1 < np) ? g_pstart[b*SEQ + p + 1] : SEQ;
    int d = threadIdx.x*4;
    float4 m = make_float4(-FLT_MAX, -FLT_MAX, -FLT_MAX, -FLT_MAX);
    const float* src = g_xn + (size_t)b*SEQ*DIM + d;
    for (int i = i0; i < i1; i++){
        float4 v = *(const float4*)(src + (size_t)i*DIM);
        m.x = fmaxf(m.x, v.x); m.y = fmaxf(m.y, v.y);
        m.z = fmaxf(m.z, v.z); m.w = fmaxf(m.w, v.w);
    }
    *(float4*)(g_pool + ((size_t)(b*SEQ + p))*DIM + d) = m;
}

// ---------------- hd = embeds + pooled[pid]  -> g_h ----------------
__global__ __launch_bounds__(256) void k_gather(){
    int bs = blockIdx.x; int b = bs / SEQ;
    int pid = g_pid[bs];
    int d = threadIdx.x*4;
    size_t o = (size_t)bs*DIM + d;
    float4 e = *(const float4*)(g_embeds + o);
    float4 pl = *(const float4*)(g_pool + ((size_t)(b*SEQ + pid))*DIM + d);
    e.x += pl.x; e.y += pl.y; e.z += pl.z; e.w += pl.w;
    *(float4*)(g_h + o) = e;
}

// ---------------- host orchestration ----------------
extern "C" void kernel_launch(void* const* d_in, const int* in_sizes, int n_in,
                              void* d_out, int out_size){
    const int*   ids  = (const int*)d_in[0];
    const float* tok  = (const float*)d_in[1];
    const float* hemb = (const float*)d_in[2];

    float *p_xn, *p_qkv, *p_attn, *p_h, *p_f13, *p_f1, *p_wt;
    cudaGetSymbolAddress((void**)&p_xn,   g_xn);
    cudaGetSymbolAddress((void**)&p_qkv,  g_qkv);
    cudaGetSymbolAddress((void**)&p_attn, g_attn);
    cudaGetSymbolAddress((void**)&p_h,    g_h);
    cudaGetSymbolAddress((void**)&p_f13,  g_f13);
    cudaGetSymbolAddress((void**)&p_f1,   g_f1);
    cudaGetSymbolAddress((void**)&p_wt,   g_wt);

    static int smem_set = 0;
    if (!smem_set){
        cudaFuncSetAttribute(k_gemm, cudaFuncAttributeMaxDynamicSharedMemorySize, GSMEM);
        smem_set = 1;
    }

    // Round weights to tf32-snapped scratch; pack qkv -> [1024,3072], w1|w3 -> [1024,5632].
    #define RND(src, dstoff, ncols, totcols, coloff, nelem) do { \
        int _n4 = (nelem)/4; \
        int _grid = (_n4 + 256*4 - 1)/(256*4); \
        k_round<<<_grid, 256>>>((src), p_wt + (dstoff), _n4, (ncols)/4, (totcols)/4, (coloff)/4); \
    } while(0)
    for (int L = 0; L < 2; L++){
        size_t base = (size_t)L*LWS;
        RND((const float*)d_in[3+10*L+0], base,            DIM, QKVS, 0,        DD);  // wq
        RND((const float*)d_in[3+10*L+1], base,            DIM, QKVS, DIM,      DD);  // wk
        RND((const float*)d_in[3+10*L+2], base,            DIM, QKVS, 2*DIM,    DD);  // wv
        RND((const float*)d_in[3+10*L+3], base+3*DD,       DIM, DIM,  0,        DD);  // wo
        RND((const float*)d_in[3+10*L+4], base+4*DD,       FF,  FF2,  0,        DF);  // w1
        RND((const float*)d_in[3+10*L+6], base+4*DD,       FF,  FF2,  FF,       DF);  // w3
        RND((const float*)d_in[3+10*L+5], base+4*DD+2*(size_t)DF, DIM, DIM, 0,  DF);  // w2
    }
    RND((const float*)d_in[23], 2*(size_t)LWS, OUTV, OUTV, 0, (size_t)DIM*OUTV);

    k_hash_embed<<<NTOK, 256>>>(ids, tok, hemb);
    k_patch<<<1, 64>>>(ids);

    for (int L = 0; L < 2; L++){
        size_t base = (size_t)L*LWS;
        float* wqkv = p_wt + base;
        float* wo   = p_wt + base + 3*DD;
        float* w13  = p_wt + base + 4*DD;
        float* w2   = p_wt + base + 4*DD + 2*(size_t)DF;
        const float* natt = (const float*)d_in[3 + 10*L + 7];
        const float* nffn = (const float*)d_in[3 + 10*L + 8];
        const float* nout = (const float*)d_in[3 + 10*L + 9];

        k_rmsnorm<<<NTOK, 256>>>(natt);
        k_gemm<<<dim3(32, 24), 128, GSMEM>>>(p_xn, wqkv, p_qkv, nullptr, QKVS, DIM, 0);
        k_rope<<<NTOK, 256>>>();
        k_attn<<<NTOK/QT, 128>>>();
        k_gemm<<<dim3(32, 8),  128, GSMEM>>>(p_attn, wo, p_h, p_h, DIM, DIM, 1);
        k_rmsnorm<<<NTOK, 256>>>(nffn);
        k_gemm<<<dim3(32, 44), 128, GSMEM>>>(p_xn, w13, p_f13, nullptr, FF2, DIM, 0);
        k_silu<<<NTOK, 704>>>();
        k_gemm<<<dim3(32, 8),  128, GSMEM>>>(p_f1, w2, p_h, p_h, DIM, FF, 1);

        if (L == 0){
            k_rmsnorm<<<NTOK, 256>>>(nout);        // g_h -> g_xn (encoder out norm)
            k_pool<<<dim3(SEQ, BB), 256>>>();      // segment max over g_xn
            k_gather<<<NTOK, 256>>>();             // g_h = embeds + pooled[pid]
        }
    }
    k_rmsnorm<<<NTOK, 256>>>((const float*)d_in[22]);  // dec_norm_out
    k_gemm<<<dim3(32, 250), 128, GSMEM>>>(p_xn, p_wt + 2*(size_t)LWS, (float*)d_out,
                                          nullptr, OUTV, DIM, 0);
}

// round 14
// speedup vs baseline: 1.0743x; 1.0743x over previous
#include <cuda_runtime.h>
#include <math.h>
#include <float.h>

#define BB 2
#define SEQ 2048
#define DIM 1024
#define FF 2816
#define NTOK (BB*SEQ)
#define WIN 512
#define OUTV 32000
#define SPACE 36
#define QKVS 3072
#define FF2  5632

#define DD   (DIM*DIM)          // 1048576
#define DF   (DIM*FF)           // 2883584
#define LWS  (4*DD + 3*DF)      // per-layer weight floats
#define WTOT (2*LWS + DIM*OUTV) // all rounded weights

// ---------------- scratch (device globals; no allocation allowed) ----------------
__device__ float g_embeds[NTOK*DIM];
__device__ float g_h[NTOK*DIM];
__device__ float g_xn[NTOK*DIM];
__device__ float g_qkv[(size_t)NTOK*QKVS];
__device__ float g_attn[NTOK*DIM];
__device__ float g_f13[(size_t)NTOK*FF2];
__device__ float g_f1[(size_t)NTOK*FF];
__device__ float g_pool[NTOK*DIM];
__device__ float g_wt[WTOT];
__device__ int   g_pid[NTOK];
__device__ int   g_pstart[NTOK];
__device__ int   g_np[BB];

__device__ __forceinline__ float rtf(float x){
    unsigned r;
    asm("cvt.rna.tf32.f32 %0, %1;" : "=r"(r) : "f"(x));
    return __uint_as_float(r);
}

// ---------------- consolidated weight rounding (tf32-snap + column packing) ----------------
// Up to 8 weight segments per launch; geometry passed by value. Same per-element
// math as the old k_round -> bit-identical packed weights.
struct RCfg {
    const float* src[8];
    long long dst4[8];        // dst offset in float4 units within g_wt
    int n4[8], nc4[8], tc4[8], co4[8];
    int bs[9];                // cumulative block starts; bs[nseg] = total blocks
    int nseg;
};

__global__ __launch_bounds__(256) void k_round_multi(RCfg c, float* __restrict__ wt){
    int blk = blockIdx.x;
    int seg = 0;
    #pragma unroll
    for (int s = 1; s < 8; s++)
        if (s < c.nseg && blk >= c.bs[s]) seg = s;
    int lb = blk - c.bs[seg];
    int e = lb*256 + threadIdx.x;
    int n4 = c.n4[seg];
    int stride = (c.bs[seg+1] - c.bs[seg])*256;
    const float4* s4 = (const float4*)c.src[seg];
    float4* d4 = (float4*)wt + c.dst4[seg];
    int nc = c.nc4[seg], tc = c.tc4[seg], co = c.co4[seg];
    float4 v[4]; int idx[4]; int cnt = 0;
    #pragma unroll
    for (int i = 0; i < 4; i++){
        int ix = e + i*stride;
        if (ix < n4){ v[cnt] = s4[ix]; idx[cnt] = ix; cnt++; }
    }
    #pragma unroll
    for (int i = 0; i < 4; i++){
        if (i < cnt){
            float4 w = v[i];
            w.x = rtf(w.x); w.y = rtf(w.y); w.z = rtf(w.z); w.w = rtf(w.w);
            int k = idx[i] / nc;
            int ccol = idx[i] - k*nc;
            d4[(size_t)k*tc + co + ccol] = w;
        }
    }
}

// ---------------- hash n-gram embeddings ----------------
__global__ __launch_bounds__(256) void k_hash_embed(const int* __restrict__ ids,
        const float* __restrict__ tok_emb, const float* __restrict__ hash_emb){
    int bs = blockIdx.x; int b = bs / SEQ; int i = bs - b*SEQ;
    const int* row = ids + b*SEQ;
    unsigned gg[4];
    #pragma unroll
    for (int j = 0; j < 4; j++) gg[j] = (i >= j) ? (unsigned)row[i-j] : 0u;
    const unsigned mult[3] = {2654435761u, 805459861u, 2246822519u};
    const float* src0 = tok_emb + (size_t)row[i]*DIM;
    const float* srch[3];
    #pragma unroll
    for (int f = 0; f < 3; f++){
        unsigned a = mult[f], h = 0u;
        #pragma unroll
        for (int j = 0; j < 4; j++) h = h*a + gg[j];
        srch[f] = hash_emb + ((size_t)f*32000u + (h % 32000u))*DIM;
    }
    int d = threadIdx.x*4;
    float4 v = *(const float4*)(src0 + d);
    #pragma unroll
    for (int f = 0; f < 3; f++){
        float4 w = *(const float4*)(srch[f] + d);
        v.x += w.x; v.y += w.y; v.z += w.z; v.w += w.w;
    }
    size_t o = (size_t)bs*DIM + d;
    *(float4*)(g_embeds + o) = v;
    *(float4*)(g_h + o) = v;
}

// ---------------- patch ids via warp scan (1 warp per batch) ----------------
__global__ void k_patch(const int* __restrict__ ids){
    int b = threadIdx.x >> 5;
    int lane = threadIdx.x & 31;
    if (b >= BB) return;
    const int* row = ids + b*SEQ;
    int base = 0;
    for (int c = 0; c < SEQ; c += 32){
        int i = c + lane;
        int s = (i == 0) || (row[i-1] == SPACE);
        unsigned m = __ballot_sync(0xffffffffu, s);
        int pid = base + __popc(m & (0xffffffffu >> (31 - lane))) - 1;
        g_pid[b*SEQ + i] = pid;
        if (s) g_pstart[b*SEQ + pid] = i;
        base += __popc(m);
    }
    if (lane == 0) g_np[b] = base;
}

// ---------------- rmsnorm: g_h -> g_xn (output tf32-snapped) ----------------
__global__ __launch_bounds__(256) void k_rmsnorm(const float* __restrict__ w){
    int rowi = blockIdx.x;
    int tid = threadIdx.x;
    size_t base = (size_t)rowi*DIM + tid*4;
    float4 v = *(const float4*)(g_h + base);
    float ss = v.x*v.x + v.y*v.y + v.z*v.z + v.w*v.w;
    #pragma unroll
    for (int o = 16; o; o >>= 1) ss += __shfl_xor_sync(0xffffffffu, ss, o);
    __shared__ float red[8];
    if ((tid & 31) == 0) red[tid >> 5] = ss;
    __syncthreads();
    float tot = red[0]+red[1]+red[2]+red[3]+red[4]+red[5]+red[6]+red[7];
    float r = rsqrtf(tot * (1.0f/DIM) + 1e-5f);
    float4 wv = *(const float4*)(w + tid*4);
    float4 o4;
    o4.x = rtf(v.x*r*wv.x); o4.y = rtf(v.y*r*wv.y);
    o4.z = rtf(v.z*r*wv.z); o4.w = rtf(v.w*r*wv.w);
    *(float4*)(g_xn + base) = o4;
}

#define CP_ASYNC16(dst, src) \
    asm volatile("cp.async.cg.shared.global [%0], [%1], 16;\n" :: "r"(dst), "l"(src))
#define CP_COMMIT() asm volatile("cp.async.commit_group;\n" ::)

#define MMA_TF32(acc, a0,a1,a2,a3, b0,b1) \
    asm volatile( \
        "mma.sync.aligned.m16n8k8.row.col.f32.tf32.tf32.f32 " \
        "{%0,%1,%2,%3}, {%4,%5,%6,%7}, {%8,%9}, {%0,%1,%2,%3};" \
        : "+f"((acc)[0]), "+f"((acc)[1]), "+f"((acc)[2]), "+f"((acc)[3]) \
        : "r"(a0), "r"(a1), "r"(a2), "r"(a3), "r"(b0), "r"(b1))

// ---------------- tf32 tensor-core GEMM (proven R11 config: 256 thr, 8 warps 64x32) ----------------
#define GSMEM (4*(128*20 + 16*136)*4)

__global__ __launch_bounds__(256, 2) void k_gemm(const float* __restrict__ A,
        const float* __restrict__ Bm, float* __restrict__ C,
        const float* __restrict__ R, int N, int K, int addres){
    extern __shared__ __align__(16) float smem[];
    float (*As)[128][20] = (float(*)[128][20])smem;
    float (*Bs)[16][136] = (float(*)[16][136])(smem + 4*128*20);

    const int m0 = blockIdx.x * 128, n0 = blockIdx.y * 128;
    const int tid = threadIdx.x;
    const int wid = tid >> 5, lane = tid & 31;
    const int wm = (wid >> 2) * 64;
    const int wn = (wid & 3) * 32;
    const int g = lane >> 2, tg = lane & 3;

    const int arow = tid >> 2, acol = (tid & 3) * 4;
    const int brow = tid >> 5, bcol = (tid & 31) * 4;
    const float* Abase = A + (size_t)(m0 + arow)*K + acol;
    const float* Bbase = Bm + (size_t)brow*N + n0 + bcol;

    float acc[4][4][4];
    #pragma unroll
    for (int i = 0; i < 4; i++)
        #pragma unroll
        for (int j = 0; j < 4; j++)
            #pragma unroll
            for (int c = 0; c < 4; c++) acc[i][j][c] = 0.0f;

#define LOADSTAGE(st, k0) do { \
        unsigned da0 = (unsigned)__cvta_generic_to_shared(&As[st][arow][acol]); \
        CP_ASYNC16(da0, Abase + (k0)); \
        unsigned da1 = (unsigned)__cvta_generic_to_shared(&As[st][arow+64][acol]); \
        CP_ASYNC16(da1, Abase + (size_t)64*K + (k0)); \
        unsigned db0 = (unsigned)__cvta_generic_to_shared(&Bs[st][brow][bcol]); \
        CP_ASYNC16(db0, Bbase + (size_t)(k0)*N); \
        unsigned db1 = (unsigned)__cvta_generic_to_shared(&Bs[st][brow+8][bcol]); \
        CP_ASYNC16(db1, Bbase + (size_t)((k0)+8)*N); \
        CP_COMMIT(); \
    } while(0)

    const int KT = K >> 4;
    LOADSTAGE(0, 0);
    LOADSTAGE(1, 16);
    LOADSTAGE(2, 32);

    for (int kt = 0; kt < KT; kt++){
        const int s = kt & 3;
        const int rem = KT - 1 - kt;
        if (rem >= 2)      asm volatile("cp.async.wait_group 2;\n" ::);
        else if (rem == 1) asm volatile("cp.async.wait_group 1;\n" ::);
        else               asm volatile("cp.async.wait_group 0;\n" ::);
        __syncthreads();
        if (kt + 3 < KT) LOADSTAGE((kt+3) & 3, (kt+3) << 4);

        #pragma unroll
        for (int kk = 0; kk < 16; kk += 8){
            unsigned af[4][4], bf[4][2];
            #pragma unroll
            for (int i = 0; i < 4; i++){
                int r = wm + i*16;
                af[i][0] = __float_as_uint(As[s][r+g   ][kk+tg  ]);
                af[i][1] = __float_as_uint(As[s][r+g+8 ][kk+tg  ]);
                af[i][2] = __float_as_uint(As[s][r+g   ][kk+tg+4]);
                af[i][3] = __float_as_uint(As[s][r+g+8 ][kk+tg+4]);
            }
            #pragma unroll
            for (int j = 0; j < 4; j++){
                int cl = wn + j*8 + g;
                bf[j][0] = __float_as_uint(Bs[s][kk+tg  ][cl]);
                bf[j][1] = __float_as_uint(Bs[s][kk+tg+4][cl]);
            }
            #pragma unroll
            for (int i = 0; i < 4; i++)
                #pragma unroll
                for (int j = 0; j < 4; j++)
                    MMA_TF32(acc[i][j], af[i][0],af[i][1],af[i][2],af[i][3],
                             bf[j][0],bf[j][1]);
        }
    }

    #pragma unroll
    for (int i = 0; i < 4; i++){
        #pragma unroll
        for (int j = 0; j < 4; j++){
            size_t off = (size_t)(m0 + wm + i*16 + g)*N + n0 + wn + j*8 + tg*2;
            float2 r0 = make_float2(acc[i][j][0], acc[i][j][1]);
            float2 r1 = make_float2(acc[i][j][2], acc[i][j][3]);
            if (addres){
                float2 q0 = *(const float2*)(R + off);
                float2 q1 = *(const float2*)(R + off + (size_t)8*N);
                r0.x += q0.x; r0.y += q0.y; r1.x += q1.x; r1.y += q1.y;
            }
            *(float2*)(C + off) = r0;
            *(float2*)(C + off + (size_t)8*N) = r1;
        }
    }
}

// ---------------- RoPE (in place on q,k inside g_qkv) ----------------
__global__ __launch_bounds__(256) void k_rope(){
    int bs = blockIdx.x;
    int pos = bs & (SEQ - 1);
    size_t base = (size_t)bs*QKVS;
    for (int d = threadIdx.x; d < 512; d += 256){
        float freq = powf(10000.0f, -(float)d * (1.0f/512.0f));
        float ang = (float)pos * freq;
        float sn, cs;
        sincosf(ang, &sn, &cs);
        float x1 = g_qkv[base + d], x2 = g_qkv[base + 512 + d];
        g_qkv[base + d]       = x1*cs - x2*sn;
        g_qkv[base + 512 + d] = x1*sn + x2*cs;
        x1 = g_qkv[base + 1024 + d]; x2 = g_qkv[base + 1536 + d];
        g_qkv[base + 1024 + d] = x1*cs - x2*sn;
        g_qkv[base + 1536 + d] = x1*sn + x2*cs;
    }
}

// ---------------- fused windowed causal attention, 16-query tiles ----------------
#define QT 16
#define SPAN 544
__global__ __launch_bounds__(128) void k_attn(){
    __shared__ __align__(16) float Ssh[QT*SPAN];   // 34.8 KB
    __shared__ __align__(16) float stage[4752];    // 19 KB
    float* Qs = stage;            // [16][33]
    float* Ks = stage + 16*33;    // [128][33]
    float* Vs = stage;            // [32][136] in pass 2
    int tile = blockIdx.x;
    int b = tile / (SEQ/QT);
    int i0 = (tile - b*(SEQ/QT)) * QT;
    int tid = threadIdx.x;
    int tq = tid >> 5, tk = tid & 31;      // warp 0..3, lane
    int kmin = i0 - (WIN - 1); if (kmin < 0) kmin = 0;
    int span = i0 + QT - kmin;                       // <= 527
    int spanw = ((span + 63) >> 6) << 6;
    if (spanw > SPAN) spanw = SPAN;
    int lastkey = i0 + QT - 1;

    // ---- pass 1: scores = Q K^T / 32 (banded, masked) ----
    for (int kc0 = 0; kc0 < span; kc0 += 128){
        float c[4][4];
        #pragma unroll
        for (int u = 0; u < 4; u++)
            #pragma unroll
            for (int v = 0; v < 4; v++) c[u][v] = 0.f;
        for (int dc = 0; dc < DIM; dc += 32){
            int r = tid >> 3, cb = (tid & 7) << 2;   // r in [0,16), cb in {0..28}
            {
                float4 qv = *(const float4*)(g_qkv + ((size_t)(b*SEQ + i0 + r))*QKVS + dc + cb);
                float* qp = Qs + r*33 + cb;
                qp[0]=qv.x; qp[1]=qv.y; qp[2]=qv.z; qp[3]=qv.w;
            }
            #pragma unroll
            for (int h = 0; h < 8; h++){             // K: 128 rows
                int rr = r + h*16;
                int key = kmin + kc0 + rr; if (key > lastkey) key = lastkey;
                float4 kv = *(const float4*)(g_qkv + ((size_t)(b*SEQ + key))*QKVS + 1024 + dc + cb);
                float* kp = Ks + rr*33 + cb;
                kp[0]=kv.x; kp[1]=kv.y; kp[2]=kv.z; kp[3]=kv.w;
            }
            __syncthreads();
            #pragma unroll
            for (int d = 0; d < 32; d++){
                float a0 = Qs[(tq*4  )*33 + d];
                float a1 = Qs[(tq*4+1)*33 + d];
                float a2 = Qs[(tq*4+2)*33 + d];
                float a3 = Qs[(tq*4+3)*33 + d];
                #pragma unroll
                for (int v = 0; v < 4; v++){
                    float bv = Ks[(tk + 32*v)*33 + d];
                    c[0][v] += a0*bv;
                    c[1][v] += a1*bv;
                    c[2][v] += a2*bv;
                    c[3][v] += a3*bv;
                }
            }
            __syncthreads();
        }
        #pragma unroll
        for (int u = 0; u < 4; u++){
            int qa = i0 + tq*4 + u;
            #pragma unroll
            for (int v = 0; v < 4; v++){
                int jr = kc0 + tk + 32*v;
                if (jr < SPAN){
                    int ja = kmin + jr;
                    bool ok = (jr < span) && (ja <= qa) && (qa - ja < WIN);
                    Ssh[(tq*4+u)*SPAN + jr] = ok ? c[u][v]*0.03125f : -1e30f;
                }
            }
        }
    }
    __syncthreads();

    // ---- softmax (4 warps, 4 rows each) ----
    for (int q = tq; q < QT; q += 4){
        float* sr = Ssh + q*SPAN;
        float mx = -1e30f;
        for (int j = tk; j < spanw; j += 32) mx = fmaxf(mx, sr[j]);
        #pragma unroll
        for (int o = 16; o; o >>= 1) mx = fmaxf(mx, __shfl_xor_sync(0xffffffffu, mx, o));
        float sm = 0.f;
        for (int j = tk; j < spanw; j += 32){
            float p = expf(sr[j] - mx); sr[j] = p; sm += p;
        }
        #pragma unroll
        for (int o = 16; o; o >>= 1) sm += __shfl_xor_sync(0xffffffffu, sm, o);
        float inv = 1.0f/sm;
        for (int j = tk; j < spanw; j += 32) sr[j] *= inv;
    }
    __syncthreads();

    // ---- pass 2: O = P @ V (output tf32-snapped for the wo GEMM) ----
    for (int n0 = 0; n0 < DIM; n0 += 128){
        float o[4][4];
        #pragma unroll
        for (int u = 0; u < 4; u++)
            #pragma unroll
            for (int v = 0; v < 4; v++) o[u][v] = 0.f;
        for (int kc0 = 0; kc0 < span; kc0 += 32){
            int r = tid >> 3, cb = (tid & 7) << 4;   // 16 floats per thread
            #pragma unroll
            for (int h = 0; h < 2; h++){             // 32 rows
                int rr = r + h*16;
                int key = kmin + kc0 + rr; if (key > lastkey) key = lastkey;
                const float* vp = g_qkv + ((size_t)(b*SEQ + key))*QKVS + 2048 + n0 + cb;
                #pragma unroll
                for (int t4 = 0; t4 < 4; t4++){
                    *(float4*)(Vs + rr*136 + cb + t4*4) = *(const float4*)(vp + t4*4);
                }
            }
            __syncthreads();
            const float* p0r = Ssh + (tq*4)*SPAN + kc0;
            #pragma unroll
            for (int jj = 0; jj < 32; jj++){
                float p0 = p0r[jj];
                float p1 = p0r[jj + SPAN];
                float p2 = p0r[jj + 2*SPAN];
                float p3 = p0r[jj + 3*SPAN];
                #pragma unroll
                for (int v = 0; v < 4; v++){
                    float vv = Vs[jj*136 + tk + 32*v];
                    o[0][v] += p0*vv;
                    o[1][v] += p1*vv;
                    o[2][v] += p2*vv;
                    o[3][v] += p3*vv;
                }
            }
            __syncthreads();
        }
        #pragma unroll
        for (int u = 0; u < 4; u++){
            size_t ob = ((size_t)(b*SEQ + i0 + tq*4 + u))*DIM + n0;
            #pragma unroll
            for (int v = 0; v < 4; v++)
                g_attn[ob + tk + 32*v] = rtf(o[u][v]);
        }
    }
}

// ---------------- silu(f13[:, :FF]) * f13[:, FF:] -> f1 (tf32-snapped) ----------------
__global__ __launch_bounds__(704) void k_silu(){
    int row = blockIdx.x;
    int col = threadIdx.x * 4;
    size_t src = (size_t)row*FF2 + col;
    float4 a = *(float4*)(g_f13 + src);
    float4 c = *(float4*)(g_f13 + src + FF);
    a.x = rtf(a.x/(1.f + expf(-a.x))*c.x);
    a.y = rtf(a.y/(1.f + expf(-a.y))*c.y);
    a.z = rtf(a.z/(1.f + expf(-a.z))*c.z);
    a.w = rtf(a.w/(1.f + expf(-a.w))*c.w);
    *(float4*)(g_f1 + (size_t)row*FF + col) = a;
}

// ---------------- segment max pooling (runs are contiguous) ----------------
__global__ __launch_bounds__(256) void k_pool(){
    int b = blockIdx.y, p = blockIdx.x;
    int np = g_np[b];
    if (p >= np) return;
    int i0 = g_pstart[b*SEQ + p];
    int i1 = (p + 1 < np) ? g_pstart[b*SEQ + p + 1] : SEQ;
    int d = threadIdx.x*4;
    float4 m = make_float4(-FLT_MAX, -FLT_MAX, -FLT_MAX, -FLT_MAX);
    const float* src = g_xn + (size_t)b*SEQ*DIM + d;
    for (int i = i0; i < i1; i++){
        float4 v = *(const float4*)(src + (size_t)i*DIM);
        m.x = fmaxf(m.x, v.x); m.y = fmaxf(m.y, v.y);
        m.z = fmaxf(m.z, v.z); m.w = fmaxf(m.w, v.w);
    }
    *(float4*)(g_pool + ((size_t)(b*SEQ + p))*DIM + d) = m;
}

// ---------------- hd = embeds + pooled[pid]  -> g_h ----------------
__global__ __launch_bounds__(256) void k_gather(){
    int bs = blockIdx.x; int b = bs / SEQ;
    int pid = g_pid[bs];
    int d = threadIdx.x*4;
    size_t o = (size_t)bs*DIM + d;
    float4 e = *(const float4*)(g_embeds + o);
    float4 pl = *(const float4*)(g_pool + ((size_t)(b*SEQ + pid))*DIM + d);
    e.x += pl.x; e.y += pl.y; e.z += pl.z; e.w += pl.w;
    *(float4*)(g_h + o) = e;
}

// ---------------- host orchestration ----------------
extern "C" void kernel_launch(void* const* d_in, const int* in_sizes, int n_in,
                              void* d_out, int out_size){
    const int*   ids  = (const int*)d_in[0];
    const float* tok  = (const float*)d_in[1];
    const float* hemb = (const float*)d_in[2];

    float *p_xn, *p_qkv, *p_attn, *p_h, *p_f13, *p_f1, *p_wt;
    cudaGetSymbolAddress((void**)&p_xn,   g_xn);
    cudaGetSymbolAddress((void**)&p_qkv,  g_qkv);
    cudaGetSymbolAddress((void**)&p_attn, g_attn);
    cudaGetSymbolAddress((void**)&p_h,    g_h);
    cudaGetSymbolAddress((void**)&p_f13,  g_f13);
    cudaGetSymbolAddress((void**)&p_f1,   g_f1);
    cudaGetSymbolAddress((void**)&p_wt,   g_wt);

    static int smem_set = 0;
    if (!smem_set){
        cudaFuncSetAttribute(k_gemm, cudaFuncAttributeMaxDynamicSharedMemorySize, GSMEM);
        smem_set = 1;
    }

    // ---- build rounding configs (7 segments for layer L, +outproj in cfgB) ----
    const int nDD4 = DD/4, nDF4 = DF/4;           // 262144, 720896
    const int bDD = nDD4/1024, bDF = nDF4/1024;   // 256, 704 blocks
    const int nOP4 = (DIM*OUTV)/4;                // 8192000
    const int bOP = nOP4/1024;                    // 8000

    RCfg cfg[2];
    for (int L = 0; L < 2; L++){
        long long base4 = (long long)L * (LWS/4);
        RCfg& c = cfg[L];
        const int srcix[7] = {0,1,2,3,4,6,5};     // wq,wk,wv,wo,w1,w3,w2
        const long long d4[7] = {base4, base4, base4, base4 + 3LL*nDD4,
                                 base4 + 4LL*nDD4, base4 + 4LL*nDD4,
                                 base4 + 4LL*nDD4 + 2LL*nDF4};
        const int n4a[7] = {nDD4,nDD4,nDD4,nDD4,nDF4,nDF4,nDF4};
        const int nca[7] = {256,256,256,256,704,704,256};
        const int tca[7] = {768,768,768,256,1408,1408,256};
        const int coa[7] = {0,256,512,0,0,704,0};
        const int blk[7] = {bDD,bDD,bDD,bDD,bDF,bDF,bDF};
        int acc = 0;
        for (int s = 0; s < 7; s++){
            c.src[s] = (const float*)d_in[3 + 10*L + srcix[s]];
            c.dst4[s] = d4[s]; c.n4[s] = n4a[s]; c.nc4[s] = nca[s];
            c.tc4[s] = tca[s]; c.co4[s] = coa[s];
            c.bs[s] = acc; acc += blk[s];
        }
        c.bs[7] = acc; c.nseg = 7;
        if (L == 1){  // append out-proj
            c.src[7] = (const float*)d_in[23];
            c.dst4[7] = 2LL*(LWS/4);
            c.n4[7] = nOP4; c.nc4[7] = 8000; c.tc4[7] = 8000; c.co4[7] = 0;
            c.bs[7] = acc; c.bs[8] = acc + bOP; c.nseg = 8;
        }
    }

    // launches 1..6: roundA, roundB, hash, patch, rmsnorm, qkv-GEMM  (ncu -s 5 lands on the GEMM)
    k_round_multi<<<cfg[0].bs[7], 256>>>(cfg[0], p_wt);
    k_round_multi<<<cfg[1].bs[8], 256>>>(cfg[1], p_wt);
    k_hash_embed<<<NTOK, 256>>>(ids, tok, hemb);
    k_patch<<<1, 64>>>(ids);

    for (int L = 0; L < 2; L++){
        size_t base = (size_t)L*LWS;
        float* wqkv = p_wt + base;
        float* wo   = p_wt + base + 3*DD;
        float* w13  = p_wt + base + 4*DD;
        float* w2   = p_wt + base + 4*DD + 2*(size_t)DF;
        const float* natt = (const float*)d_in[3 + 10*L + 7];
        const float* nffn = (const float*)d_in[3 + 10*L + 8];
        const float* nout = (const float*)d_in[3 + 10*L + 9];

        k_rmsnorm<<<NTOK, 256>>>(natt);
        k_gemm<<<dim3(32, 24), 256, GSMEM>>>(p_xn, wqkv, p_qkv, nullptr, QKVS, DIM, 0);
        k_rope<<<NTOK, 256>>>();
        k_attn<<<NTOK/QT, 128>>>();
        k_gemm<<<dim3(32, 8),  256, GSMEM>>>(p_attn, wo, p_h, p_h, DIM, DIM, 1);
        k_rmsnorm<<<NTOK, 256>>>(nffn);
        k_gemm<<<dim3(32, 44), 256, GSMEM>>>(p_xn, w13, p_f13, nullptr, FF2, DIM, 0);
        k_silu<<<NTOK, 704>>>();
        k_gemm<<<dim3(32, 8),  256, GSMEM>>>(p_f1, w2, p_h, p_h, DIM, FF, 1);

        if (L == 0){
            k_rmsnorm<<<NTOK, 256>>>(nout);        // g_h -> g_xn (encoder out norm)
            k_pool<<<dim3(SEQ, BB), 256>>>();      // segment max over g_xn
            k_gather<<<NTOK, 256>>>();             // g_h = embeds + pooled[pid]
        }
    }
    k_rmsnorm<<<NTOK, 256>>>((const float*)d_in[22]);  // dec_norm_out
    k_gemm<<<dim3(32, 250), 256, GSMEM>>>(p_xn, p_wt + 2*(size_t)LWS, (float*)d_out,
                                          nullptr, OUTV, DIM, 0);
}

// round 16
// speedup vs baseline: 1.4860x; 1.3832x over previous
#include <cuda_runtime.h>
#include <cuda_fp16.h>
#include <math.h>
#include <float.h>

#define BB 2
#define SEQ 2048
#define DIM 1024
#define FF 2816
#define NTOK (BB*SEQ)
#define WIN 512
#define OUTV 32000
#define SPACE 36
#define QKVS 3072
#define FF2  5632

#define DD   (DIM*DIM)          // 1048576
#define DF   (DIM*FF)           // 2883584
#define LWS  (4*DD + 3*DF)      // per-layer weight halves (packed)
#define WTOT (2*LWS + DIM*OUTV)

// ---------------- scratch (device globals; no allocation allowed) ----------------
__device__ float  g_embeds[NTOK*DIM];
__device__ float  g_h[NTOK*DIM];
__device__ float  g_xn[NTOK*DIM];
__device__ float  g_qkv[(size_t)NTOK*QKVS];
__device__ float  g_f13[(size_t)NTOK*FF2];
__device__ float  g_pool[NTOK*DIM];
__device__ __half g_xnh[NTOK*DIM];
__device__ __half g_attnh[NTOK*DIM];
__device__ __half g_f1h[(size_t)NTOK*FF];
__device__ __half g_wt[WTOT];
__device__ int    g_pid[NTOK];
__device__ int    g_pstart[NTOK];
__device__ int    g_np[BB];

// ---------------- consolidated weight convert: f32 [K][N] -> k-pair half2 [K/2][N] ----------------
struct RCfg {
    const float* src[8];
    long long dst4[8];        // dst offset in uint4 (8 halves) units within g_wt
    int n4[8];                // number of quads (each quad = 4 n at one kp)
    int nc4[8];               // quads per kp row (= N/4, also src row stride in float4)
    int tc4[8];               // dst uint4 per row (= totN/4)
    int co4[8];               // dst column offset in uint4
    int bs[9];
    int nseg;
};

__global__ __launch_bounds__(256) void k_round_multi(RCfg c, __half* __restrict__ wt){
    int blk = blockIdx.x;
    int seg = 0;
    #pragma unroll
    for (int s = 1; s < 8; s++)
        if (s < c.nseg && blk >= c.bs[s]) seg = s;
    int lb = blk - c.bs[seg];
    int e = lb*256 + threadIdx.x;
    int n4 = c.n4[seg];
    int stride = (c.bs[seg+1] - c.bs[seg])*256;
    const float4* s4 = (const float4*)c.src[seg];
    uint4* d4 = (uint4*)wt + c.dst4[seg];
    int nc = c.nc4[seg], tc = c.tc4[seg], co = c.co4[seg];
    #pragma unroll
    for (int i = 0; i < 4; i++){
        int q = e + i*stride;
        if (q < n4){
            int kp = q / nc;
            int nq = q - kp*nc;
            float4 r0 = s4[(size_t)(2*kp)*nc + nq];
            float4 r1 = s4[(size_t)(2*kp+1)*nc + nq];
            __half2 h0 = __halves2half2(__float2half_rn(r0.x), __float2half_rn(r1.x));
            __half2 h1 = __halves2half2(__float2half_rn(r0.y), __float2half_rn(r1.y));
            __half2 h2 = __halves2half2(__float2half_rn(r0.z), __float2half_rn(r1.z));
            __half2 h3 = __halves2half2(__float2half_rn(r0.w), __float2half_rn(r1.w));
            uint4 o;
            o.x = *(unsigned*)&h0; o.y = *(unsigned*)&h1;
            o.z = *(unsigned*)&h2; o.w = *(unsigned*)&h3;
            d4[(size_t)kp*tc + co + nq] = o;
        }
    }
}

// ---------------- hash n-gram embeddings ----------------
__global__ __launch_bounds__(256) void k_hash_embed(const int* __restrict__ ids,
        const float* __restrict__ tok_emb, const float* __restrict__ hash_emb){
    int bs = blockIdx.x; int b = bs / SEQ; int i = bs - b*SEQ;
    const int* row = ids + b*SEQ;
    unsigned gg[4];
    #pragma unroll
    for (int j = 0; j < 4; j++) gg[j] = (i >= j) ? (unsigned)row[i-j] : 0u;
    const unsigned mult[3] = {2654435761u, 805459861u, 2246822519u};
    const float* src0 = tok_emb + (size_t)row[i]*DIM;
    const float* srch[3];
    #pragma unroll
    for (int f = 0; f < 3; f++){
        unsigned a = mult[f], h = 0u;
        #pragma unroll
        for (int j = 0; j < 4; j++) h = h*a + gg[j];
        srch[f] = hash_emb + ((size_t)f*32000u + (h % 32000u))*DIM;
    }
    int d = threadIdx.x*4;
    float4 v = *(const float4*)(src0 + d);
    #pragma unroll
    for (int f = 0; f < 3; f++){
        float4 w = *(const float4*)(srch[f] + d);
        v.x += w.x; v.y += w.y; v.z += w.z; v.w += w.w;
    }
    size_t o = (size_t)bs*DIM + d;
    *(float4*)(g_embeds + o) = v;
    *(float4*)(g_h + o) = v;
}

// ---------------- patch ids via warp scan (1 warp per batch) ----------------
__global__ void k_patch(const int* __restrict__ ids){
    int b = threadIdx.x >> 5;
    int lane = threadIdx.x & 31;
    if (b >= BB) return;
    const int* row = ids + b*SEQ;
    int base = 0;
    for (int c = 0; c < SEQ; c += 32){
        int i = c + lane;
        int s = (i == 0) || (row[i-1] == SPACE);
        unsigned m = __ballot_sync(0xffffffffu, s);
        int pid = base + __popc(m & (0xffffffffu >> (31 - lane))) - 1;
        g_pid[b*SEQ + i] = pid;
        if (s) g_pstart[b*SEQ + pid] = i;
        base += __popc(m);
    }
    if (lane == 0) g_np[b] = base;
}

// ---------------- rmsnorm: g_h -> g_xn (f32) + g_xnh (fp16) ----------------
__global__ __launch_bounds__(256) void k_rmsnorm(const float* __restrict__ w){
    int rowi = blockIdx.x;
    int tid = threadIdx.x;
    size_t base = (size_t)rowi*DIM + tid*4;
    float4 v = *(const float4*)(g_h + base);
    float ss = v.x*v.x + v.y*v.y + v.z*v.z + v.w*v.w;
    #pragma unroll
    for (int o = 16; o; o >>= 1) ss += __shfl_xor_sync(0xffffffffu, ss, o);
    __shared__ float red[8];
    if ((tid & 31) == 0) red[tid >> 5] = ss;
    __syncthreads();
    float tot = red[0]+red[1]+red[2]+red[3]+red[4]+red[5]+red[6]+red[7];
    float r = rsqrtf(tot * (1.0f/DIM) + 1e-5f);
    float4 wv = *(const float4*)(w + tid*4);
    float4 o4;
    o4.x = v.x*r*wv.x; o4.y = v.y*r*wv.y; o4.z = v.z*r*wv.z; o4.w = v.w*r*wv.w;
    *(float4*)(g_xn + base) = o4;
    __half2 h0 = __halves2half2(__float2half_rn(o4.x), __float2half_rn(o4.y));
    __half2 h1 = __halves2half2(__float2half_rn(o4.z), __float2half_rn(o4.w));
    uint2 p; p.x = *(unsigned*)&h0; p.y = *(unsigned*)&h1;
    *(uint2*)(g_xnh + base) = p;
}

#define CP_ASYNC16(dst, src) \
    asm volatile("cp.async.cg.shared.global [%0], [%1], 16;\n" :: "r"(dst), "l"(src))
#define CP_COMMIT() asm volatile("cp.async.commit_group;\n" ::)

#define MMA_F16(acc, a0,a1,a2,a3, b0,b1) \
    asm volatile( \
        "mma.sync.aligned.m16n8k16.row.col.f32.f16.f16.f32 " \
        "{%0,%1,%2,%3}, {%4,%5,%6,%7}, {%8,%9}, {%0,%1,%2,%3};" \
        : "+f"((acc)[0]), "+f"((acc)[1]), "+f"((acc)[2]), "+f"((acc)[3]) \
        : "r"(a0), "r"(a1), "r"(a2), "r"(a3), "r"(b0), "r"(b1))

// ---------------- fp16 tensor-core GEMM: 128x128x32 chunks, 8 warps of 64x32 ----------------
#define GSMEM (4*(128*40*2 + 16*136*4))

__global__ __launch_bounds__(256, 2) void k_gemm(const __half* __restrict__ A,
        const __half2* __restrict__ Bm, float* __restrict__ C,
        const float* __restrict__ R, int N, int K, int addres){
    extern __shared__ __align__(16) char smemc[];
    __half  (*As)[128][40]  = (__half(*)[128][40])smemc;
    __half2 (*Bs)[16][136]  = (__half2(*)[16][136])(smemc + 4*128*40*2);

    const int m0 = blockIdx.x * 128, n0 = blockIdx.y * 128;
    const int tid = threadIdx.x;
    const int wid = tid >> 5, lane = tid & 31;
    const int wm = (wid >> 2) * 64;
    const int wn = (wid & 3) * 32;
    const int g = lane >> 2, tg = lane & 3;

    const int arow = tid >> 1, apos = (tid & 1) * 8;   // halves
    const int brow = tid >> 4, bq   = (tid & 15) * 4;  // half2
    const __half* Abase = A + (size_t)(m0 + arow)*K + apos;
    const __half2* Bbase = Bm + (size_t)brow*N + n0 + bq;

    float acc[4][4][4];
    #pragma unroll
    for (int i = 0; i < 4; i++)
        #pragma unroll
        for (int j = 0; j < 4; j++)
            #pragma unroll
            for (int c = 0; c < 4; c++) acc[i][j][c] = 0.0f;

#define LOADSTAGE(st, k0) do { \
        unsigned da0 = (unsigned)__cvta_generic_to_shared(&As[st][arow][apos]); \
        CP_ASYNC16(da0, Abase + (k0)); \
        unsigned da1 = (unsigned)__cvta_generic_to_shared(&As[st][arow][apos+16]); \
        CP_ASYNC16(da1, Abase + (k0) + 16); \
        unsigned db0 = (unsigned)__cvta_generic_to_shared(&Bs[st][brow][bq]); \
        CP_ASYNC16(db0, Bbase + (size_t)((k0) >> 1)*N); \
        unsigned db1 = (unsigned)__cvta_generic_to_shared(&Bs[st][brow][bq+64]); \
        CP_ASYNC16(db1, Bbase + (size_t)((k0) >> 1)*N + 64); \
        CP_COMMIT(); \
    } while(0)

    const int KT = K >> 5;                 // chunks of 32 k
    LOADSTAGE(0, 0);
    LOADSTAGE(1, 32);
    LOADSTAGE(2, 64);

    for (int kt = 0; kt < KT; kt++){
        const int s = kt & 3;
        const int rem = KT - 1 - kt;
        if (rem >= 2)      asm volatile("cp.async.wait_group 2;\n" ::);
        else if (rem == 1) asm volatile("cp.async.wait_group 1;\n" ::);
        else               asm volatile("cp.async.wait_group 0;\n" ::);
        __syncthreads();
        if (kt + 3 < KT) LOADSTAGE((kt+3) & 3, (kt+3) << 5);

        #pragma unroll
        for (int kk = 0; kk < 2; kk++){    // two k16 sub-steps
            unsigned af[4][4], bf[4][2];
            #pragma unroll
            for (int i = 0; i < 4; i++){
                int r = wm + i*16;
                af[i][0] = *(const unsigned*)&As[s][r+g   ][kk*16 + 2*tg    ];
                af[i][1] = *(const unsigned*)&As[s][r+g+8 ][kk*16 + 2*tg    ];
                af[i][2] = *(const unsigned*)&As[s][r+g   ][kk*16 + 2*tg + 8];
                af[i][3] = *(const unsigned*)&As[s][r+g+8 ][kk*16 + 2*tg + 8];
            }
            #pragma unroll
            for (int j = 0; j < 4; j++){
                int cl = wn + j*8 + g;
                bf[j][0] = *(const unsigned*)&Bs[s][kk*8 + tg    ][cl];
                bf[j][1] = *(const unsigned*)&Bs[s][kk*8 + tg + 4][cl];
            }
            #pragma unroll
            for (int i = 0; i < 4; i++)
                #pragma unroll
                for (int j = 0; j < 4; j++)
                    MMA_F16(acc[i][j], af[i][0],af[i][1],af[i][2],af[i][3],
                            bf[j][0],bf[j][1]);
        }
    }

    #pragma unroll
    for (int i = 0; i < 4; i++){
        #pragma unroll
        for (int j = 0; j < 4; j++){
            size_t off = (size_t)(m0 + wm + i*16 + g)*N + n0 + wn + j*8 + tg*2;
            float2 r0 = make_float2(acc[i][j][0], acc[i][j][1]);
            float2 r1 = make_float2(acc[i][j][2], acc[i][j][3]);
            if (addres){
                float2 q0 = *(const float2*)(R + off);
                float2 q1 = *(const float2*)(R + off + (size_t)8*N);
                r0.x += q0.x; r0.y += q0.y; r1.x += q1.x; r1.y += q1.y;
            }
            *(float2*)(C + off) = r0;
            *(float2*)(C + off + (size_t)8*N) = r1;
        }
    }
}

// ---------------- RoPE (in place on q,k inside g_qkv) ----------------
__global__ __launch_bounds__(256) void k_rope(){
    int bs = blockIdx.x;
    int pos = bs & (SEQ - 1);
    size_t base = (size_t)bs*QKVS;
    for (int d = threadIdx.x; d < 512; d += 256){
        float freq = powf(10000.0f, -(float)d * (1.0f/512.0f));
        float ang = (float)pos * freq;
        float sn, cs;
        sincosf(ang, &sn, &cs);
        float x1 = g_qkv[base + d], x2 = g_qkv[base + 512 + d];
        g_qkv[base + d]       = x1*cs - x2*sn;
        g_qkv[base + 512 + d] = x1*sn + x2*cs;
        x1 = g_qkv[base + 1024 + d]; x2 = g_qkv[base + 1536 + d];
        g_qkv[base + 1024 + d] = x1*cs - x2*sn;
        g_qkv[base + 1536 + d] = x1*sn + x2*cs;
    }
}

// ---------------- fused windowed causal attention (outputs fp16 for wo GEMM) ----------------
#define QT 16
#define SPAN 544
__global__ __launch_bounds__(128) void k_attn(){
    __shared__ __align__(16) float Ssh[QT*SPAN];
    __shared__ __align__(16) float stage[4752];
    float* Qs = stage;
    float* Ks = stage + 16*33;
    float* Vs = stage;
    int tile = blockIdx.x;
    int b = tile / (SEQ/QT);
    int i0 = (tile - b*(SEQ/QT)) * QT;
    int tid = threadIdx.x;
    int tq = tid >> 5, tk = tid & 31;
    int kmin = i0 - (WIN - 1); if (kmin < 0) kmin = 0;
    int span = i0 + QT - kmin;
    int spanw = ((span + 63) >> 6) << 6;
    if (spanw > SPAN) spanw = SPAN;
    int lastkey = i0 + QT - 1;

    for (int kc0 = 0; kc0 < span; kc0 += 128){
        float c[4][4];
        #pragma unroll
        for (int u = 0; u < 4; u++)
            #pragma unroll
            for (int v = 0; v < 4; v++) c[u][v] = 0.f;
        for (int dc = 0; dc < DIM; dc += 32){
            int r = tid >> 3, cb = (tid & 7) << 2;
            {
                float4 qv = *(const float4*)(g_qkv + ((size_t)(b*SEQ + i0 + r))*QKVS + dc + cb);
                float* qp = Qs + r*33 + cb;
                qp[0]=qv.x; qp[1]=qv.y; qp[2]=qv.z; qp[3]=qv.w;
            }
            #pragma unroll
            for (int h = 0; h < 8; h++){
                int rr = r + h*16;
                int key = kmin + kc0 + rr; if (key > lastkey) key = lastkey;
                float4 kv = *(const float4*)(g_qkv + ((size_t)(b*SEQ + key))*QKVS + 1024 + dc + cb);
                float* kp = Ks + rr*33 + cb;
                kp[0]=kv.x; kp[1]=kv.y; kp[2]=kv.z; kp[3]=kv.w;
            }
            __syncthreads();
            #pragma unroll
            for (int d = 0; d < 32; d++){
                float a0 = Qs[(tq*4  )*33 + d];
                float a1 = Qs[(tq*4+1)*33 + d];
                float a2 = Qs[(tq*4+2)*33 + d];
                float a3 = Qs[(tq*4+3)*33 + d];
                #pragma unroll
                for (int v = 0; v < 4; v++){
                    float bv = Ks[(tk + 32*v)*33 + d];
                    c[0][v] += a0*bv;
                    c[1][v] += a1*bv;
                    c[2][v] += a2*bv;
                    c[3][v] += a3*bv;
                }
            }
            __syncthreads();
        }
        #pragma unroll
        for (int u = 0; u < 4; u++){
            int qa = i0 + tq*4 + u;
            #pragma unroll
            for (int v = 0; v < 4; v++){
                int jr = kc0 + tk + 32*v;
                if (jr < SPAN){
                    int ja = kmin + jr;
                    bool ok = (jr < span) && (ja <= qa) && (qa - ja < WIN);
                    Ssh[(tq*4+u)*SPAN + jr] = ok ? c[u][v]*0.03125f : -1e30f;
                }
            }
        }
    }
    __syncthreads();

    for (int q = tq; q < QT; q += 4){
        float* sr = Ssh + q*SPAN;
        float mx = -1e30f;
        for (int j = tk; j < spanw; j += 32) mx = fmaxf(mx, sr[j]);
        #pragma unroll
        for (int o = 16; o; o >>= 1) mx = fmaxf(mx, __shfl_xor_sync(0xffffffffu, mx, o));
        float sm = 0.f;
        for (int j = tk; j < spanw; j += 32){
            float p = expf(sr[j] - mx); sr[j] = p; sm += p;
        }
        #pragma unroll
        for (int o = 16; o; o >>= 1) sm += __shfl_xor_sync(0xffffffffu, sm, o);
        float inv = 1.0f/sm;
        for (int j = tk; j < spanw; j += 32) sr[j] *= inv;
    }
    __syncthreads();

    for (int n0 = 0; n0 < DIM; n0 += 128){
        float o[4][4];
        #pragma unroll
        for (int u = 0; u < 4; u++)
            #pragma unroll
            for (int v = 0; v < 4; v++) o[u][v] = 0.f;
        for (int kc0 = 0; kc0 < span; kc0 += 32){
            int r = tid >> 3, cb = (tid & 7) << 4;
            #pragma unroll
            for (int h = 0; h < 2; h++){
                int rr = r + h*16;
                int key = kmin + kc0 + rr; if (key > lastkey) key = lastkey;
                const float* vp = g_qkv + ((size_t)(b*SEQ + key))*QKVS + 2048 + n0 + cb;
                #pragma unroll
                for (int t4 = 0; t4 < 4; t4++){
                    *(float4*)(Vs + rr*136 + cb + t4*4) = *(const float4*)(vp + t4*4);
                }
            }
            __syncthreads();
            const float* p0r = Ssh + (tq*4)*SPAN + kc0;
            #pragma unroll
            for (int jj = 0; jj < 32; jj++){
                float p0 = p0r[jj];
                float p1 = p0r[jj + SPAN];
                float p2 = p0r[jj + 2*SPAN];
                float p3 = p0r[jj + 3*SPAN];
                #pragma unroll
                for (int v = 0; v < 4; v++){
                    float vv = Vs[jj*136 + tk + 32*v];
                    o[0][v] += p0*vv;
                    o[1][v] += p1*vv;
                    o[2][v] += p2*vv;
                    o[3][v] += p3*vv;
                }
            }
            __syncthreads();
        }
        #pragma unroll
        for (int u = 0; u < 4; u++){
            size_t ob = ((size_t)(b*SEQ + i0 + tq*4 + u))*DIM + n0;
            #pragma unroll
            for (int v = 0; v < 4; v++)
                g_attnh[ob + tk + 32*v] = __float2half_rn(o[u][v]);
        }
    }
}

// ---------------- silu(f13[:, :FF]) * f13[:, FF:] -> g_f1h fp16 ----------------
__global__ __launch_bounds__(704) void k_silu(){
    int row = blockIdx.x;
    int col = threadIdx.x * 4;
    size_t src = (size_t)row*FF2 + col;
    float4 a = *(float4*)(g_f13 + src);
    float4 c = *(float4*)(g_f13 + src + FF);
    a.x = a.x/(1.f + expf(-a.x))*c.x;
    a.y = a.y/(1.f + expf(-a.y))*c.y;
    a.z = a.z/(1.f + expf(-a.z))*c.z;
    a.w = a.w/(1.f + expf(-a.w))*c.w;
    __half2 h0 = __halves2half2(__float2half_rn(a.x), __float2half_rn(a.y));
    __half2 h1 = __halves2half2(__float2half_rn(a.z), __float2half_rn(a.w));
    uint2 p; p.x = *(unsigned*)&h0; p.y = *(unsigned*)&h1;
    *(uint2*)(g_f1h + (size_t)row*FF + col) = p;
}

// ---------------- segment max pooling ----------------
__global__ __launch_bounds__(256) void k_pool(){
    int b = blockIdx.y, p = blockIdx.x;
    int np = g_np[b];
    if (p >= np) return;
    int i0 = g_pstart[b*SEQ + p];
    int i1 = (p + 1 < np) ? g_pstart[b*SEQ + p + 1] : SEQ;
    int d = threadIdx.x*4;
    float4 m = make_float4(-FLT_MAX, -FLT_MAX, -FLT_MAX, -FLT_MAX);
    const float* src = g_xn + (size_t)b*SEQ*DIM + d;
    for (int i = i0; i < i1; i++){
        float4 v = *(const float4*)(src + (size_t)i*DIM);
        m.x = fmaxf(m.x, v.x); m.y = fmaxf(m.y, v.y);
        m.z = fmaxf(m.z, v.z); m.w = fmaxf(m.w, v.w);
    }
    *(float4*)(g_pool + ((size_t)(b*SEQ + p))*DIM + d) = m;
}

// ---------------- hd = embeds + pooled[pid]  -> g_h ----------------
__global__ __launch_bounds__(256) void k_gather(){
    int bs = blockIdx.x; int b = bs / SEQ;
    int pid = g_pid[bs];
    int d = threadIdx.x*4;
    size_t o = (size_t)bs*DIM + d;
    float4 e = *(const float4*)(g_embeds + o);
    float4 pl = *(const float4*)(g_pool + ((size_t)(b*SEQ + pid))*DIM + d);
    e.x += pl.x; e.y += pl.y; e.z += pl.z; e.w += pl.w;
    *(float4*)(g_h + o) = e;
}

// ---------------- host orchestration ----------------
extern "C" void kernel_launch(void* const* d_in, const int* in_sizes, int n_in,
                              void* d_out, int out_size){
    const int*   ids  = (const int*)d_in[0];
    const float* tok  = (const float*)d_in[1];
    const float* hemb = (const float*)d_in[2];

    float *p_xn, *p_qkv, *p_h, *p_f13;
    __half *p_xnh, *p_attnh, *p_f1h, *p_wt;
    cudaGetSymbolAddress((void**)&p_xn,    g_xn);
    cudaGetSymbolAddress((void**)&p_qkv,   g_qkv);
    cudaGetSymbolAddress((void**)&p_h,     g_h);
    cudaGetSymbolAddress((void**)&p_f13,   g_f13);
    cudaGetSymbolAddress((void**)&p_xnh,   g_xnh);
    cudaGetSymbolAddress((void**)&p_attnh, g_attnh);
    cudaGetSymbolAddress((void**)&p_f1h,   g_f1h);
    cudaGetSymbolAddress((void**)&p_wt,    g_wt);

    static int smem_set = 0;
    if (!smem_set){
        cudaFuncSetAttribute(k_gemm, cudaFuncAttributeMaxDynamicSharedMemorySize, GSMEM);
        smem_set = 1;
    }

    // ---- rounding configs: quads = (K/2)*(N/4) per segment ----
    const int qDD = (DIM/2)*(DIM/4);        // 131072
    const int qDF = (DIM/2)*(FF/4);         // 360448 (w1/w3)
    const int qW2 = (FF/2)*(DIM/4);         // 360448
    const int qOP = (DIM/2)*(OUTV/4);       // 4096000
    const int bDD = qDD/1024, bDF = qDF/1024, bW2 = qW2/1024, bOP = qOP/1024;

    RCfg cfg[2];
    for (int L = 0; L < 2; L++){
        long long b8 = (long long)L * (LWS/8);
        RCfg& c = cfg[L];
        const int srcix[7] = {0,1,2,3,4,6,5};     // wq,wk,wv,wo,w1,w3,w2
        const long long d4[7] = {b8, b8, b8, b8 + 3LL*DD/8,
                                 b8 + 4LL*DD/8, b8 + 4LL*DD/8,
                                 b8 + (4LL*DD + 2LL*DF)/8};
        const int n4a[7] = {qDD,qDD,qDD,qDD,qDF,qDF,qW2};
        const int nca[7] = {256,256,256,256,704,704,256};
        const int tca[7] = {768,768,768,256,1408,1408,256};
        const int coa[7] = {0,256,512,0,0,704,0};
        const int blk[7] = {bDD,bDD,bDD,bDD,bDF,bDF,bW2};
        int acc = 0;
        for (int s = 0; s < 7; s++){
            c.src[s] = (const float*)d_in[3 + 10*L + srcix[s]];
            c.dst4[s] = d4[s]; c.n4[s] = n4a[s]; c.nc4[s] = nca[s];
            c.tc4[s] = tca[s]; c.co4[s] = coa[s];
            c.bs[s] = acc; acc += blk[s];
        }
        c.bs[7] = acc; c.nseg = 7;
        if (L == 1){
            c.src[7] = (const float*)d_in[23];
            c.dst4[7] = 2LL*(LWS/8);
            c.n4[7] = qOP; c.nc4[7] = 8000; c.tc4[7] = 8000; c.co4[7] = 0;
            c.bs[7] = acc; c.bs[8] = acc + bOP; c.nseg = 8;
        }
    }

    k_round_multi<<<cfg[0].bs[7], 256>>>(cfg[0], p_wt);
    k_round_multi<<<cfg[1].bs[8], 256>>>(cfg[1], p_wt);
    k_hash_embed<<<NTOK, 256>>>(ids, tok, hemb);
    k_patch<<<1, 64>>>(ids);

    for (int L = 0; L < 2; L++){
        size_t base = (size_t)L*LWS;
        __half2* wqkv = (__half2*)(p_wt + base);
        __half2* wo   = (__half2*)(p_wt + base + 3*(size_t)DD);
        __half2* w13  = (__half2*)(p_wt + base + 4*(size_t)DD);
        __half2* w2   = (__half2*)(p_wt + base + 4*(size_t)DD + 2*(size_t)DF);
        const float* natt = (const float*)d_in[3 + 10*L + 7];
        const float* nffn = (const float*)d_in[3 + 10*L + 8];
        const float* nout = (const float*)d_in[3 + 10*L + 9];

        k_rmsnorm<<<NTOK, 256>>>(natt);
        k_gemm<<<dim3(32, 24), 256, GSMEM>>>(p_xnh, wqkv, p_qkv, nullptr, QKVS, DIM, 0);
        k_rope<<<NTOK, 256>>>();
        k_attn<<<NTOK/QT, 128>>>();
        k_gemm<<<dim3(32, 8),  256, GSMEM>>>(p_attnh, wo, p_h, p_h, DIM, DIM, 1);
        k_rmsnorm<<<NTOK, 256>>>(nffn);
        k_gemm<<<dim3(32, 44), 256, GSMEM>>>(p_xnh, w13, p_f13, nullptr, FF2, DIM, 0);
        k_silu<<<NTOK, 704>>>();
        k_gemm<<<dim3(32, 8),  256, GSMEM>>>(p_f1h, w2, p_h, p_h, DIM, FF, 1);

        if (L == 0){
            k_rmsnorm<<<NTOK, 256>>>(nout);
            k_pool<<<dim3(SEQ, BB), 256>>>();
            k_gather<<<NTOK, 256>>>();
        }
    }
    k_rmsnorm<<<NTOK, 256>>>((const float*)d_in[22]);
    k_gemm<<<dim3(32, 250), 256, GSMEM>>>(p_xnh, (__half2*)(p_wt + 2*(size_t)LWS),
                                          (float*)d_out, nullptr, OUTV, DIM, 0);
}

// round 17
// speedup vs baseline: 1.5345x; 1.0327x over previous
#include <cuda_runtime.h>
#include <cuda_fp16.h>
#include <math.h>
#include <float.h>

#define BB 2
#define SEQ 2048
#define DIM 1024
#define FF 2816
#define NTOK (BB*SEQ)
#define WIN 512
#define OUTV 32000
#define SPACE 36
#define QKVS 3072
#define FF2  5632

#define DD   (DIM*DIM)          // 1048576
#define DF   (DIM*FF)           // 2883584
#define LWS  (4*DD + 3*DF)      // per-layer weight halves (packed)
#define WTOT (2*LWS + DIM*OUTV)

// ---------------- scratch (device globals; no allocation allowed) ----------------
__device__ float  g_embeds[NTOK*DIM];
__device__ float  g_h[NTOK*DIM];
__device__ float  g_xn[NTOK*DIM];
__device__ float  g_pool[NTOK*DIM];
__device__ __half g_qkvh[(size_t)NTOK*QKVS];
__device__ __half g_f13h[(size_t)NTOK*FF2];
__device__ __half g_xnh[NTOK*DIM];
__device__ __half g_attnh[NTOK*DIM];
__device__ __half g_f1h[(size_t)NTOK*FF];
__device__ __half g_wt[WTOT];
__device__ int    g_pid[NTOK];
__device__ int    g_pstart[NTOK];
__device__ int    g_np[BB];

// ---------------- consolidated weight convert: f32 [K][N] -> k-pair half2 [K/2][N] ----------------
struct RCfg {
    const float* src[8];
    long long dst4[8];        // dst offset in uint4 (8 halves) units within g_wt
    int n4[8];                // number of quads (each quad = 4 n at one kp)
    int nc4[8];               // quads per kp row (= N/4, also src row stride in float4)
    int tc4[8];               // dst uint4 per row (= totN/4)
    int co4[8];               // dst column offset in uint4
    int bs[9];
    int nseg;
};

__global__ __launch_bounds__(256) void k_round_multi(RCfg c, __half* __restrict__ wt){
    int blk = blockIdx.x;
    int seg = 0;
    #pragma unroll
    for (int s = 1; s < 8; s++)
        if (s < c.nseg && blk >= c.bs[s]) seg = s;
    int lb = blk - c.bs[seg];
    int e = lb*256 + threadIdx.x;
    int n4 = c.n4[seg];
    int stride = (c.bs[seg+1] - c.bs[seg])*256;
    const float4* s4 = (const float4*)c.src[seg];
    uint4* d4 = (uint4*)wt + c.dst4[seg];
    int nc = c.nc4[seg], tc = c.tc4[seg], co = c.co4[seg];
    #pragma unroll
    for (int i = 0; i < 4; i++){
        int q = e + i*stride;
        if (q < n4){
            int kp = q / nc;
            int nq = q - kp*nc;
            float4 r0 = s4[(size_t)(2*kp)*nc + nq];
            float4 r1 = s4[(size_t)(2*kp+1)*nc + nq];
            __half2 h0 = __halves2half2(__float2half_rn(r0.x), __float2half_rn(r1.x));
            __half2 h1 = __halves2half2(__float2half_rn(r0.y), __float2half_rn(r1.y));
            __half2 h2 = __halves2half2(__float2half_rn(r0.z), __float2half_rn(r1.z));
            __half2 h3 = __halves2half2(__float2half_rn(r0.w), __float2half_rn(r1.w));
            uint4 o;
            o.x = *(unsigned*)&h0; o.y = *(unsigned*)&h1;
            o.z = *(unsigned*)&h2; o.w = *(unsigned*)&h3;
            d4[(size_t)kp*tc + co + nq] = o;
        }
    }
}

// ---------------- hash n-gram embeddings ----------------
__global__ __launch_bounds__(256) void k_hash_embed(const int* __restrict__ ids,
        const float* __restrict__ tok_emb, const float* __restrict__ hash_emb){
    int bs = blockIdx.x; int b = bs / SEQ; int i = bs - b*SEQ;
    const int* row = ids + b*SEQ;
    unsigned gg[4];
    #pragma unroll
    for (int j = 0; j < 4; j++) gg[j] = (i >= j) ? (unsigned)row[i-j] : 0u;
    const unsigned mult[3] = {2654435761u, 805459861u, 2246822519u};
    const float* src0 = tok_emb + (size_t)row[i]*DIM;
    const float* srch[3];
    #pragma unroll
    for (int f = 0; f < 3; f++){
        unsigned a = mult[f], h = 0u;
        #pragma unroll
        for (int j = 0; j < 4; j++) h = h*a + gg[j];
        srch[f] = hash_emb + ((size_t)f*32000u + (h % 32000u))*DIM;
    }
    int d = threadIdx.x*4;
    float4 v = *(const float4*)(src0 + d);
    #pragma unroll
    for (int f = 0; f < 3; f++){
        float4 w = *(const float4*)(srch[f] + d);
        v.x += w.x; v.y += w.y; v.z += w.z; v.w += w.w;
    }
    size_t o = (size_t)bs*DIM + d;
    *(float4*)(g_embeds + o) = v;
    *(float4*)(g_h + o) = v;
}

// ---------------- patch ids via warp scan (1 warp per batch) ----------------
__global__ void k_patch(const int* __restrict__ ids){
    int b = threadIdx.x >> 5;
    int lane = threadIdx.x & 31;
    if (b >= BB) return;
    const int* row = ids + b*SEQ;
    int base = 0;
    for (int c = 0; c < SEQ; c += 32){
        int i = c + lane;
        int s = (i == 0) || (row[i-1] == SPACE);
        unsigned m = __ballot_sync(0xffffffffu, s);
        int pid = base + __popc(m & (0xffffffffu >> (31 - lane))) - 1;
        g_pid[b*SEQ + i] = pid;
        if (s) g_pstart[b*SEQ + pid] = i;
        base += __popc(m);
    }
    if (lane == 0) g_np[b] = base;
}

// ---------------- rmsnorm: g_h -> g_xn (f32) + g_xnh (fp16) ----------------
__global__ __launch_bounds__(256) void k_rmsnorm(const float* __restrict__ w){
    int rowi = blockIdx.x;
    int tid = threadIdx.x;
    size_t base = (size_t)rowi*DIM + tid*4;
    float4 v = *(const float4*)(g_h + base);
    float ss = v.x*v.x + v.y*v.y + v.z*v.z + v.w*v.w;
    #pragma unroll
    for (int o = 16; o; o >>= 1) ss += __shfl_xor_sync(0xffffffffu, ss, o);
    __shared__ float red[8];
    if ((tid & 31) == 0) red[tid >> 5] = ss;
    __syncthreads();
    float tot = red[0]+red[1]+red[2]+red[3]+red[4]+red[5]+red[6]+red[7];
    float r = rsqrtf(tot * (1.0f/DIM) + 1e-5f);
    float4 wv = *(const float4*)(w + tid*4);
    float4 o4;
    o4.x = v.x*r*wv.x; o4.y = v.y*r*wv.y; o4.z = v.z*r*wv.z; o4.w = v.w*r*wv.w;
    *(float4*)(g_xn + base) = o4;
    __half2 h0 = __halves2half2(__float2half_rn(o4.x), __float2half_rn(o4.y));
    __half2 h1 = __halves2half2(__float2half_rn(o4.z), __float2half_rn(o4.w));
    uint2 p; p.x = *(unsigned*)&h0; p.y = *(unsigned*)&h1;
    *(uint2*)(g_xnh + base) = p;
}

#define CP_ASYNC16(dst, src) \
    asm volatile("cp.async.cg.shared.global [%0], [%1], 16;\n" :: "r"(dst), "l"(src))
#define CP_COMMIT() asm volatile("cp.async.commit_group;\n" ::)

#define MMA_F16(acc, a0,a1,a2,a3, b0,b1) \
    asm volatile( \
        "mma.sync.aligned.m16n8k16.row.col.f32.f16.f16.f32 " \
        "{%0,%1,%2,%3}, {%4,%5,%6,%7}, {%8,%9}, {%0,%1,%2,%3};" \
        : "+f"((acc)[0]), "+f"((acc)[1]), "+f"((acc)[2]), "+f"((acc)[3]) \
        : "r"(a0), "r"(a1), "r"(a2), "r"(a3), "r"(b0), "r"(b1))

// ---------------- fp16 tensor-core GEMM: 128x128x32 chunks, 8 warps of 64x32 ----------------
// A: half [M][K] row-major. B: packed half2 [K/2][N]. C: f32 (+residual) or fp16.
#define GSMEM (4*(128*40*2 + 16*136*4))

__global__ __launch_bounds__(256, 2) void k_gemm(const __half* __restrict__ A,
        const __half2* __restrict__ Bm, void* __restrict__ Cv,
        const float* __restrict__ R, int N, int K, int addres, int outhalf){
    extern __shared__ __align__(16) char smemc[];
    __half  (*As)[128][40]  = (__half(*)[128][40])smemc;
    __half2 (*Bs)[16][136]  = (__half2(*)[16][136])(smemc + 4*128*40*2);

    const int m0 = blockIdx.x * 128, n0 = blockIdx.y * 128;
    const int tid = threadIdx.x;
    const int wid = tid >> 5, lane = tid & 31;
    const int wm = (wid >> 2) * 64;
    const int wn = (wid & 3) * 32;
    const int g = lane >> 2, tg = lane & 3;

    const int arow = tid >> 1, apos = (tid & 1) * 8;   // halves
    const int brow = tid >> 4, bq   = (tid & 15) * 4;  // half2
    const __half* Abase = A + (size_t)(m0 + arow)*K + apos;
    const __half2* Bbase = Bm + (size_t)brow*N + n0 + bq;

    float acc[4][4][4];
    #pragma unroll
    for (int i = 0; i < 4; i++)
        #pragma unroll
        for (int j = 0; j < 4; j++)
            #pragma unroll
            for (int c = 0; c < 4; c++) acc[i][j][c] = 0.0f;

#define LOADSTAGE(st, k0) do { \
        unsigned da0 = (unsigned)__cvta_generic_to_shared(&As[st][arow][apos]); \
        CP_ASYNC16(da0, Abase + (k0)); \
        unsigned da1 = (unsigned)__cvta_generic_to_shared(&As[st][arow][apos+16]); \
        CP_ASYNC16(da1, Abase + (k0) + 16); \
        unsigned db0 = (unsigned)__cvta_generic_to_shared(&Bs[st][brow][bq]); \
        CP_ASYNC16(db0, Bbase + (size_t)((k0) >> 1)*N); \
        unsigned db1 = (unsigned)__cvta_generic_to_shared(&Bs[st][brow][bq+64]); \
        CP_ASYNC16(db1, Bbase + (size_t)((k0) >> 1)*N + 64); \
        CP_COMMIT(); \
    } while(0)

    const int KT = K >> 5;                 // chunks of 32 k
    LOADSTAGE(0, 0);
    LOADSTAGE(1, 32);
    LOADSTAGE(2, 64);

    for (int kt = 0; kt < KT; kt++){
        const int s = kt & 3;
        const int rem = KT - 1 - kt;
        if (rem >= 2)      asm volatile("cp.async.wait_group 2;\n" ::);
        else if (rem == 1) asm volatile("cp.async.wait_group 1;\n" ::);
        else               asm volatile("cp.async.wait_group 0;\n" ::);
        __syncthreads();
        if (kt + 3 < KT) LOADSTAGE((kt+3) & 3, (kt+3) << 5);

        #pragma unroll
        for (int kk = 0; kk < 2; kk++){    // two k16 sub-steps
            unsigned af[4][4], bf[4][2];
            #pragma unroll
            for (int i = 0; i < 4; i++){
                int r = wm + i*16;
                af[i][0] = *(const unsigned*)&As[s][r+g   ][kk*16 + 2*tg    ];
                af[i][1] = *(const unsigned*)&As[s][r+g+8 ][kk*16 + 2*tg    ];
                af[i][2] = *(const unsigned*)&As[s][r+g   ][kk*16 + 2*tg + 8];
                af[i][3] = *(const unsigned*)&As[s][r+g+8 ][kk*16 + 2*tg + 8];
            }
            #pragma unroll
            for (int j = 0; j < 4; j++){
                int cl = wn + j*8 + g;
                bf[j][0] = *(const unsigned*)&Bs[s][kk*8 + tg    ][cl];
                bf[j][1] = *(const unsigned*)&Bs[s][kk*8 + tg + 4][cl];
            }
            #pragma unroll
            for (int i = 0; i < 4; i++)
                #pragma unroll
                for (int j = 0; j < 4; j++)
                    MMA_F16(acc[i][j], af[i][0],af[i][1],af[i][2],af[i][3],
                            bf[j][0],bf[j][1]);
        }
    }

    #pragma unroll
    for (int i = 0; i < 4; i++){
        #pragma unroll
        for (int j = 0; j < 4; j++){
            size_t off = (size_t)(m0 + wm + i*16 + g)*N + n0 + wn + j*8 + tg*2;
            if (outhalf){
                __half* Ch = (__half*)Cv;
                __half2 hh0 = __halves2half2(__float2half_rn(acc[i][j][0]),
                                             __float2half_rn(acc[i][j][1]));
                __half2 hh1 = __halves2half2(__float2half_rn(acc[i][j][2]),
                                             __float2half_rn(acc[i][j][3]));
                *(unsigned*)(Ch + off) = *(unsigned*)&hh0;
                *(unsigned*)(Ch + off + (size_t)8*N) = *(unsigned*)&hh1;
            } else {
                float* C = (float*)Cv;
                float2 r0 = make_float2(acc[i][j][0], acc[i][j][1]);
                float2 r1 = make_float2(acc[i][j][2], acc[i][j][3]);
                if (addres){
                    float2 q0 = *(const float2*)(R + off);
                    float2 q1 = *(const float2*)(R + off + (size_t)8*N);
                    r0.x += q0.x; r0.y += q0.y; r1.x += q1.x; r1.y += q1.y;
                }
                *(float2*)(C + off) = r0;
                *(float2*)(C + off + (size_t)8*N) = r1;
            }
        }
    }
}

// ---------------- RoPE (in place on fp16 q,k inside g_qkvh) ----------------
__global__ __launch_bounds__(256) void k_rope(){
    int bs = blockIdx.x;
    int pos = bs & (SEQ - 1);
    size_t base = (size_t)bs*QKVS;
    for (int d = threadIdx.x; d < 512; d += 256){
        float freq = powf(10000.0f, -(float)d * (1.0f/512.0f));
        float ang = (float)pos * freq;
        float sn, cs;
        sincosf(ang, &sn, &cs);
        float x1 = __half2float(g_qkvh[base + d]);
        float x2 = __half2float(g_qkvh[base + 512 + d]);
        g_qkvh[base + d]       = __float2half_rn(x1*cs - x2*sn);
        g_qkvh[base + 512 + d] = __float2half_rn(x1*sn + x2*cs);
        x1 = __half2float(g_qkvh[base + 1024 + d]);
        x2 = __half2float(g_qkvh[base + 1536 + d]);
        g_qkvh[base + 1024 + d] = __float2half_rn(x1*cs - x2*sn);
        g_qkvh[base + 1536 + d] = __float2half_rn(x1*sn + x2*cs);
    }
}

// ---------------- fused windowed causal attention (fp16 in, fp16 out, f32 math) ----------------
#define QT 16
#define SPAN 544
__global__ __launch_bounds__(128) void k_attn(){
    __shared__ __align__(16) float Ssh[QT*SPAN];
    __shared__ __align__(16) float stage[4752];
    float* Qs = stage;
    float* Ks = stage + 16*33;
    float* Vs = stage;
    int tile = blockIdx.x;
    int b = tile / (SEQ/QT);
    int i0 = (tile - b*(SEQ/QT)) * QT;
    int tid = threadIdx.x;
    int tq = tid >> 5, tk = tid & 31;
    int kmin = i0 - (WIN - 1); if (kmin < 0) kmin = 0;
    int span = i0 + QT - kmin;
    int spanw = ((span + 63) >> 6) << 6;
    if (spanw > SPAN) spanw = SPAN;
    int lastkey = i0 + QT - 1;

    for (int kc0 = 0; kc0 < span; kc0 += 128){
        float c[4][4];
        #pragma unroll
        for (int u = 0; u < 4; u++)
            #pragma unroll
            for (int v = 0; v < 4; v++) c[u][v] = 0.f;
        for (int dc = 0; dc < DIM; dc += 32){
            int r = tid >> 3, cb = (tid & 7) << 2;
            {
                uint2 qv = *(const uint2*)(g_qkvh + ((size_t)(b*SEQ + i0 + r))*QKVS + dc + cb);
                float2 f0 = __half22float2(*(__half2*)&qv.x);
                float2 f1 = __half22float2(*(__half2*)&qv.y);
                float* qp = Qs + r*33 + cb;
                qp[0]=f0.x; qp[1]=f0.y; qp[2]=f1.x; qp[3]=f1.y;
            }
            #pragma unroll
            for (int h = 0; h < 8; h++){
                int rr = r + h*16;
                int key = kmin + kc0 + rr; if (key > lastkey) key = lastkey;
                uint2 kv = *(const uint2*)(g_qkvh + ((size_t)(b*SEQ + key))*QKVS + 1024 + dc + cb);
                float2 f0 = __half22float2(*(__half2*)&kv.x);
                float2 f1 = __half22float2(*(__half2*)&kv.y);
                float* kp = Ks + rr*33 + cb;
                kp[0]=f0.x; kp[1]=f0.y; kp[2]=f1.x; kp[3]=f1.y;
            }
            __syncthreads();
            #pragma unroll
            for (int d = 0; d < 32; d++){
                float a0 = Qs[(tq*4  )*33 + d];
                float a1 = Qs[(tq*4+1)*33 + d];
                float a2 = Qs[(tq*4+2)*33 + d];
                float a3 = Qs[(tq*4+3)*33 + d];
                #pragma unroll
                for (int v = 0; v < 4; v++){
                    float bv = Ks[(tk + 32*v)*33 + d];
                    c[0][v] += a0*bv;
                    c[1][v] += a1*bv;
                    c[2][v] += a2*bv;
                    c[3][v] += a3*bv;
                }
            }
            __syncthreads();
        }
        #pragma unroll
        for (int u = 0; u < 4; u++){
            int qa = i0 + tq*4 + u;
            #pragma unroll
            for (int v = 0; v < 4; v++){
                int jr = kc0 + tk + 32*v;
                if (jr < SPAN){
                    int ja = kmin + jr;
                    bool ok = (jr < span) && (ja <= qa) && (qa - ja < WIN);
                    Ssh[(tq*4+u)*SPAN + jr] = ok ? c[u][v]*0.03125f : -1e30f;
                }
            }
        }
    }
    __syncthreads();

    for (int q = tq; q < QT; q += 4){
        float* sr = Ssh + q*SPAN;
        float mx = -1e30f;
        for (int j = tk; j < spanw; j += 32) mx = fmaxf(mx, sr[j]);
        #pragma unroll
        for (int o = 16; o; o >>= 1) mx = fmaxf(mx, __shfl_xor_sync(0xffffffffu, mx, o));
        float sm = 0.f;
        for (int j = tk; j < spanw; j += 32){
            float p = expf(sr[j] - mx); sr[j] = p; sm += p;
        }
        #pragma unroll
        for (int o = 16; o; o >>= 1) sm += __shfl_xor_sync(0xffffffffu, sm, o);
        float inv = 1.0f/sm;
        for (int j = tk; j < spanw; j += 32) sr[j] *= inv;
    }
    __syncthreads();

    for (int n0 = 0; n0 < DIM; n0 += 128){
        float o[4][4];
        #pragma unroll
        for (int u = 0; u < 4; u++)
            #pragma unroll
            for (int v = 0; v < 4; v++) o[u][v] = 0.f;
        for (int kc0 = 0; kc0 < span; kc0 += 32){
            int r = tid >> 3, cb = (tid & 7) << 4;
            #pragma unroll
            for (int h = 0; h < 2; h++){
                int rr = r + h*16;
                int key = kmin + kc0 + rr; if (key > lastkey) key = lastkey;
                const __half* vp = g_qkvh + ((size_t)(b*SEQ + key))*QKVS + 2048 + n0 + cb;
                uint4 vv0 = *(const uint4*)vp;         // 8 halves
                uint4 vv1 = *(const uint4*)(vp + 8);   // 8 halves
                float* dst = Vs + rr*136 + cb;
                float2 f;
                f = __half22float2(*(__half2*)&vv0.x); dst[0]=f.x;  dst[1]=f.y;
                f = __half22float2(*(__half2*)&vv0.y); dst[2]=f.x;  dst[3]=f.y;
                f = __half22float2(*(__half2*)&vv0.z); dst[4]=f.x;  dst[5]=f.y;
                f = __half22float2(*(__half2*)&vv0.w); dst[6]=f.x;  dst[7]=f.y;
                f = __half22float2(*(__half2*)&vv1.x); dst[8]=f.x;  dst[9]=f.y;
                f = __half22float2(*(__half2*)&vv1.y); dst[10]=f.x; dst[11]=f.y;
                f = __half22float2(*(__half2*)&vv1.z); dst[12]=f.x; dst[13]=f.y;
                f = __half22float2(*(__half2*)&vv1.w); dst[14]=f.x; dst[15]=f.y;
            }
            __syncthreads();
            const float* p0r = Ssh + (tq*4)*SPAN + kc0;
            #pragma unroll
            for (int jj = 0; jj < 32; jj++){
                float p0 = p0r[jj];
                float p1 = p0r[jj + SPAN];
                float p2 = p0r[jj + 2*SPAN];
                float p3 = p0r[jj + 3*SPAN];
                #pragma unroll
                for (int v = 0; v < 4; v++){
                    float vv = Vs[jj*136 + tk + 32*v];
                    o[0][v] += p0*vv;
                    o[1][v] += p1*vv;
                    o[2][v] += p2*vv;
                    o[3][v] += p3*vv;
                }
            }
            __syncthreads();
        }
        #pragma unroll
        for (int u = 0; u < 4; u++){
            size_t ob = ((size_t)(b*SEQ + i0 + tq*4 + u))*DIM + n0;
            #pragma unroll
            for (int v = 0; v < 4; v++)
                g_attnh[ob + tk + 32*v] = __float2half_rn(o[u][v]);
        }
    }
}

// ---------------- silu(f13h[:, :FF]) * f13h[:, FF:] -> g_f1h fp16 ----------------
__global__ __launch_bounds__(704) void k_silu(){
    int row = blockIdx.x;
    int col = threadIdx.x * 4;
    const __half* s = g_f13h + (size_t)row*FF2 + col;
    uint2 av = *(const uint2*)s;
    uint2 cv = *(const uint2*)(s + FF);
    float2 a0 = __half22float2(*(__half2*)&av.x);
    float2 a1 = __half22float2(*(__half2*)&av.y);
    float2 c0 = __half22float2(*(__half2*)&cv.x);
    float2 c1 = __half22float2(*(__half2*)&cv.y);
    a0.x = a0.x/(1.f + expf(-a0.x))*c0.x;
    a0.y = a0.y/(1.f + expf(-a0.y))*c0.y;
    a1.x = a1.x/(1.f + expf(-a1.x))*c1.x;
    a1.y = a1.y/(1.f + expf(-a1.y))*c1.y;
    __half2 h0 = __halves2half2(__float2half_rn(a0.x), __float2half_rn(a0.y));
    __half2 h1 = __halves2half2(__float2half_rn(a1.x), __float2half_rn(a1.y));
    uint2 p; p.x = *(unsigned*)&h0; p.y = *(unsigned*)&h1;
    *(uint2*)(g_f1h + (size_t)row*FF + col) = p;
}

// ---------------- segment max pooling ----------------
__global__ __launch_bounds__(256) void k_pool(){
    int b = blockIdx.y, p = blockIdx.x;
    int np = g_np[b];
    if (p >= np) return;
    int i0 = g_pstart[b*SEQ + p];
    int i1 = (p + 1 < np) ? g_pstart[b*SEQ + p + 1] : SEQ;
    int d = threadIdx.x*4;
    float4 m = make_float4(-FLT_MAX, -FLT_MAX, -FLT_MAX, -FLT_MAX);
    const float* src = g_xn + (size_t)b*SEQ*DIM + d;
    for (int i = i0; i < i1; i++){
        float4 v = *(const float4*)(src + (size_t)i*DIM);
        m.x = fmaxf(m.x, v.x); m.y = fmaxf(m.y, v.y);
        m.z = fmaxf(m.z, v.z); m.w = fmaxf(m.w, v.w);
    }
    *(float4*)(g_pool + ((size_t)(b*SEQ + p))*DIM + d) = m;
}

// ---------------- hd = embeds + pooled[pid]  -> g_h ----------------
__global__ __launch_bounds__(256) void k_gather(){
    int bs = blockIdx.x; int b = bs / SEQ;
    int pid = g_pid[bs];
    int d = threadIdx.x*4;
    size_t o = (size_t)bs*DIM + d;
    float4 e = *(const float4*)(g_embeds + o);
    float4 pl = *(const float4*)(g_pool + ((size_t)(b*SEQ + pid))*DIM + d);
    e.x += pl.x; e.y += pl.y; e.z += pl.z; e.w += pl.w;
    *(float4*)(g_h + o) = e;
}

// ---------------- host orchestration ----------------
extern "C" void kernel_launch(void* const* d_in, const int* in_sizes, int n_in,
                              void* d_out, int out_size){
    const int*   ids  = (const int*)d_in[0];
    const float* tok  = (const float*)d_in[1];
    const float* hemb = (const float*)d_in[2];

    float *p_h;
    __half *p_xnh, *p_attnh, *p_f1h, *p_wt, *p_qkvh, *p_f13h;
    cudaGetSymbolAddress((void**)&p_h,     g_h);
    cudaGetSymbolAddress((void**)&p_xnh,   g_xnh);
    cudaGetSymbolAddress((void**)&p_attnh, g_attnh);
    cudaGetSymbolAddress((void**)&p_f1h,   g_f1h);
    cudaGetSymbolAddress((void**)&p_wt,    g_wt);
    cudaGetSymbolAddress((void**)&p_qkvh,  g_qkvh);
    cudaGetSymbolAddress((void**)&p_f13h,  g_f13h);

    static int smem_set = 0;
    if (!smem_set){
        cudaFuncSetAttribute(k_gemm, cudaFuncAttributeMaxDynamicSharedMemorySize, GSMEM);
        smem_set = 1;
    }

    // ---- rounding configs: quads = (K/2)*(N/4) per segment ----
    const int qDD = (DIM/2)*(DIM/4);
    const int qDF = (DIM/2)*(FF/4);
    const int qW2 = (FF/2)*(DIM/4);
    const int qOP = (DIM/2)*(OUTV/4);
    const int bDD = qDD/1024, bDF = qDF/1024, bW2 = qW2/1024, bOP = qOP/1024;

    RCfg cfg[2];
    for (int L = 0; L < 2; L++){
        long long b8 = (long long)L * (LWS/8);
        RCfg& c = cfg[L];
        const int srcix[7] = {0,1,2,3,4,6,5};     // wq,wk,wv,wo,w1,w3,w2
        const long long d4[7] = {b8, b8, b8, b8 + 3LL*DD/8,
                                 b8 + 4LL*DD/8, b8 + 4LL*DD/8,
                                 b8 + (4LL*DD + 2LL*DF)/8};
        const int n4a[7] = {qDD,qDD,qDD,qDD,qDF,qDF,qW2};
        const int nca[7] = {256,256,256,256,704,704,256};
        const int tca[7] = {768,768,768,256,1408,1408,256};
        const int coa[7] = {0,256,512,0,0,704,0};
        const int blk[7] = {bDD,bDD,bDD,bDD,bDF,bDF,bW2};
        int acc = 0;
        for (int s = 0; s < 7; s++){
            c.src[s] = (const float*)d_in[3 + 10*L + srcix[s]];
            c.dst4[s] = d4[s]; c.n4[s] = n4a[s]; c.nc4[s] = nca[s];
            c.tc4[s] = tca[s]; c.co4[s] = coa[s];
            c.bs[s] = acc; acc += blk[s];
        }
        c.bs[7] = acc; c.nseg = 7;
        if (L == 1){
            c.src[7] = (const float*)d_in[23];
            c.dst4[7] = 2LL*(LWS/8);
            c.n4[7] = qOP; c.nc4[7] = 8000; c.tc4[7] = 8000; c.co4[7] = 0;
            c.bs[7] = acc; c.bs[8] = acc + bOP; c.nseg = 8;
        }
    }

    k_round_multi<<<cfg[0].bs[7], 256>>>(cfg[0], p_wt);
    k_round_multi<<<cfg[1].bs[8], 256>>>(cfg[1], p_wt);
    k_hash_embed<<<NTOK, 256>>>(ids, tok, hemb);
    k_patch<<<1, 64>>>(ids);

    for (int L = 0; L < 2; L++){
        size_t base = (size_t)L*LWS;
        __half2* wqkv = (__half2*)(p_wt + base);
        __half2* wo   = (__half2*)(p_wt + base + 3*(size_t)DD);
        __half2* w13  = (__half2*)(p_wt + base + 4*(size_t)DD);
        __half2* w2   = (__half2*)(p_wt + base + 4*(size_t)DD + 2*(size_t)DF);
        const float* natt = (const float*)d_in[3 + 10*L + 7];
        const float* nffn = (const float*)d_in[3 + 10*L + 8];
        const float* nout = (const float*)d_in[3 + 10*L + 9];

        k_rmsnorm<<<NTOK, 256>>>(natt);
        k_gemm<<<dim3(32, 24), 256, GSMEM>>>(p_xnh, wqkv, p_qkvh, nullptr, QKVS, DIM, 0, 1);
        k_rope<<<NTOK, 256>>>();
        k_attn<<<NTOK/QT, 128>>>();
        k_gemm<<<dim3(32, 8),  256, GSMEM>>>(p_attnh, wo, p_h, p_h, DIM, DIM, 1, 0);
        k_rmsnorm<<<NTOK, 256>>>(nffn);
        k_gemm<<<dim3(32, 44), 256, GSMEM>>>(p_xnh, w13, p_f13h, nullptr, FF2, DIM, 0, 1);
        k_silu<<<NTOK, 704>>>();
        k_gemm<<<dim3(32, 8),  256, GSMEM>>>(p_f1h, w2, p_h, p_h, DIM, FF, 1, 0);

        if (L == 0){
            k_rmsnorm<<<NTOK, 256>>>(nout);
            k_pool<<<dim3(SEQ, BB), 256>>>();
            k_gather<<<NTOK, 256>>>();
        }
    }
    k_rmsnorm<<<NTOK, 256>>>((const float*)d_in[22]);
    k_gemm<<<dim3(32, 250), 256, GSMEM>>>(p_xnh, (__half2*)(p_wt + 2*(size_t)LWS),
                                          (float*)d_out, nullptr, OUTV, DIM, 0, 0);
}